// round 1
// baseline (speedup 1.0000x reference)
#include <cuda_runtime.h>
#include <math.h>

// Problem constants
#define BB   16
#define CC   512
#define TT   1024        // 32*32
#define NH   8
#define HD   64          // head dim
#define NG   32          // groups
#define CPG  16          // channels per group
#define M_QKV 1536

// Scratch (device globals; no allocations allowed)
__device__ float g_xn  [(size_t)BB * CC * TT];        // 32 MB
__device__ float g_qkv [(size_t)BB * M_QKV * TT];     // 96 MB
__device__ float g_attn[(size_t)BB * CC * TT];        // 32 MB

// ---------------------------------------------------------------------------
// GroupNorm: one block per (b, g). Group data is contiguous: 16 ch * 1024.
// ---------------------------------------------------------------------------
__global__ __launch_bounds__(256) void gn_kernel(
    const float* __restrict__ x, const float* __restrict__ sc,
    const float* __restrict__ bi, float* __restrict__ xn)
{
    int b = blockIdx.x >> 5;
    int g = blockIdx.x & 31;
    const float* base  = x  + ((size_t)b * CC + g * CPG) * TT;
    float*       obase = xn + ((size_t)b * CC + g * CPG) * TT;
    int tid = threadIdx.x;

    float s = 0.f, ss = 0.f;
    for (int i = tid; i < 4096; i += 256) {
        float4 v = *(const float4*)(base + (size_t)i * 4);
        s  += v.x + v.y + v.z + v.w;
        ss += v.x * v.x + v.y * v.y + v.z * v.z + v.w * v.w;
    }
    __shared__ float rs[8], rss[8];
    #pragma unroll
    for (int off = 16; off >= 1; off >>= 1) {
        s  += __shfl_xor_sync(0xffffffffu, s,  off);
        ss += __shfl_xor_sync(0xffffffffu, ss, off);
    }
    int warp = tid >> 5, lane = tid & 31;
    if (lane == 0) { rs[warp] = s; rss[warp] = ss; }
    __syncthreads();
    if (warp == 0) {
        s  = (lane < 8) ? rs[lane]  : 0.f;
        ss = (lane < 8) ? rss[lane] : 0.f;
        #pragma unroll
        for (int off = 4; off >= 1; off >>= 1) {
            s  += __shfl_xor_sync(0xffffffffu, s,  off);
            ss += __shfl_xor_sync(0xffffffffu, ss, off);
        }
        if (lane == 0) { rs[0] = s; rss[0] = ss; }
    }
    __syncthreads();
    float mu   = rs[0] * (1.f / 16384.f);
    float var  = rss[0] * (1.f / 16384.f) - mu * mu;
    float rstd = rsqrtf(var + 1e-5f);

    for (int i = tid; i < 4096; i += 256) {
        int c    = g * CPG + (i >> 8);         // (i*4)/1024
        float a  = rstd * sc[c];
        float b2 = bi[c] - mu * a;
        float4 v = *(const float4*)(base + (size_t)i * 4);
        v.x = v.x * a + b2; v.y = v.y * a + b2;
        v.z = v.z * a + b2; v.w = v.w * a + b2;
        *(float4*)(obase + (size_t)i * 4) = v;
    }
}

// ---------------------------------------------------------------------------
// SGEMM: out[b][m][n] = sum_k W[m][k] * X[b][k][n] + bias[m] (+ res[b][m][n])
// 64x64 block tile, k-step 16, 256 threads, 4x4 register micro-tile.
// ---------------------------------------------------------------------------
__global__ __launch_bounds__(256) void sgemm_kernel(
    const float* __restrict__ W, const float* __restrict__ X,
    const float* __restrict__ bias, const float* __restrict__ res,
    float* __restrict__ out, int M, int K, int N)
{
    __shared__ float As[16][68];   // [kk][m]  (A transposed)
    __shared__ float Bs[16][68];   // [kk][n]

    int tid = threadIdx.x;
    int m0 = blockIdx.y * 64, n0 = blockIdx.x * 64;
    size_t bb = blockIdx.z;
    const float* Xb   = X   + bb * (size_t)K * N;
    float*       outb = out + bb * (size_t)M * N;

    int ty = tid >> 4, tx = tid & 15;
    int my = ty * 4,  nx = tx * 4;
    int arow = tid >> 2,  akq = (tid & 3) << 2;
    int brow = tid >> 4,  bnq = (tid & 15) << 2;

    float acc[4][4] = {};

    for (int k0 = 0; k0 < K; k0 += 16) {
        float4 w4 = *(const float4*)(W  + (size_t)(m0 + arow) * K + k0 + akq);
        float4 x4 = *(const float4*)(Xb + (size_t)(k0 + brow) * N + n0 + bnq);
        As[akq + 0][arow] = w4.x;
        As[akq + 1][arow] = w4.y;
        As[akq + 2][arow] = w4.z;
        As[akq + 3][arow] = w4.w;
        *(float4*)&Bs[brow][bnq] = x4;
        __syncthreads();
        #pragma unroll
        for (int kk = 0; kk < 16; kk++) {
            float4 a = *(float4*)&As[kk][my];
            float4 b = *(float4*)&Bs[kk][nx];
            float av[4] = {a.x, a.y, a.z, a.w};
            float bv[4] = {b.x, b.y, b.z, b.w};
            #pragma unroll
            for (int i = 0; i < 4; i++)
                #pragma unroll
                for (int j = 0; j < 4; j++)
                    acc[i][j] += av[i] * bv[j];
        }
        __syncthreads();
    }

    #pragma unroll
    for (int i = 0; i < 4; i++) {
        float bv = bias[m0 + my + i];
        size_t off = (size_t)(m0 + my + i) * N + n0 + nx;
        float4 r = make_float4(acc[i][0] + bv, acc[i][1] + bv,
                               acc[i][2] + bv, acc[i][3] + bv);
        if (res) {
            float4 rr = *(const float4*)(res + bb * (size_t)M * N + off);
            r.x += rr.x; r.y += rr.y; r.z += rr.z; r.w += rr.w;
        }
        *(float4*)(outb + off) = r;
    }
}

// ---------------------------------------------------------------------------
// Flash attention (fp32): one block per (t-tile of 64, head, batch).
// qkv layout: [b][o][t], o = s*512 + h*64 + d  (s = 0:q, 1:k, 2:v)
// ---------------------------------------------------------------------------
#define ATS 68  // smem row stride (floats); 68%4==0 for aligned float4

__global__ __launch_bounds__(256) void attn_kernel(
    const float* __restrict__ qkv, float* __restrict__ attn_out)
{
    extern __shared__ float sm[];
    float* Qs = sm;              // [d][m]   64 x ATS
    float* Ks = Qs + 64 * ATS;   // [d][s]
    float* Vs = Ks + 64 * ATS;   // [dou][s]
    float* Ps = Vs + 64 * ATS;   // [m][s]; reused as [dou][m] in epilogue

    int t0 = blockIdx.x * 64;
    int h  = blockIdx.y;
    int b  = blockIdx.z;
    const float* qb = qkv + ((size_t)b * M_QKV + h * HD) * TT;
    const float* kb = qb + (size_t)CC * TT;
    const float* vb = qb + (size_t)2 * CC * TT;

    int tid = threadIdx.x;
    int ty = tid >> 4, tx = tid & 15;
    int my = ty * 4,  nx = tx * 4;
    const float scale = 0.125f;  // 1/sqrt(64)

    // Load Q tile, pre-scaled
    for (int idx = tid; idx < 64 * 16; idx += 256) {
        int d = idx >> 4; int mq = (idx & 15) << 2;
        float4 v = *(const float4*)(qb + (size_t)d * TT + t0 + mq);
        v.x *= scale; v.y *= scale; v.z *= scale; v.w *= scale;
        *(float4*)(Qs + d * ATS + mq) = v;
    }

    float Oa[4][4] = {};
    float m_r[4], l_r[4];
    #pragma unroll
    for (int i = 0; i < 4; i++) { m_r[i] = -1e30f; l_r[i] = 0.f; }

    for (int n0 = 0; n0 < TT; n0 += 64) {
        __syncthreads();   // previous O-accum done before overwriting K/V
        for (int idx = tid; idx < 64 * 16; idx += 256) {
            int d = idx >> 4; int sq = (idx & 15) << 2;
            *(float4*)(Ks + d * ATS + sq) =
                *(const float4*)(kb + (size_t)d * TT + n0 + sq);
            *(float4*)(Vs + d * ATS + sq) =
                *(const float4*)(vb + (size_t)d * TT + n0 + sq);
        }
        __syncthreads();

        // S[m][n] = sum_d Q[d][m] * K[d][n]
        float s[4][4] = {};
        #pragma unroll 16
        for (int d = 0; d < 64; d++) {
            float4 a = *(float4*)(Qs + d * ATS + my);
            float4 bq = *(float4*)(Ks + d * ATS + nx);
            float av[4] = {a.x, a.y, a.z, a.w};
            float bv[4] = {bq.x, bq.y, bq.z, bq.w};
            #pragma unroll
            for (int i = 0; i < 4; i++)
                #pragma unroll
                for (int j = 0; j < 4; j++)
                    s[i][j] += av[i] * bv[j];
        }

        // Online softmax (row groups = 16 lanes sharing ty)
        #pragma unroll
        for (int i = 0; i < 4; i++) {
            float tmax = fmaxf(fmaxf(s[i][0], s[i][1]), fmaxf(s[i][2], s[i][3]));
            #pragma unroll
            for (int off = 8; off >= 1; off >>= 1)
                tmax = fmaxf(tmax, __shfl_xor_sync(0xffffffffu, tmax, off));
            float nm   = fmaxf(m_r[i], tmax);
            float corr = __expf(m_r[i] - nm);
            float rs = 0.f;
            #pragma unroll
            for (int j = 0; j < 4; j++) { s[i][j] = __expf(s[i][j] - nm); rs += s[i][j]; }
            #pragma unroll
            for (int off = 8; off >= 1; off >>= 1)
                rs += __shfl_xor_sync(0xffffffffu, rs, off);
            l_r[i] = l_r[i] * corr + rs;
            m_r[i] = nm;
            #pragma unroll
            for (int j = 0; j < 4; j++) Oa[i][j] *= corr;
            *(float4*)(Ps + (my + i) * ATS + nx) =
                make_float4(s[i][0], s[i][1], s[i][2], s[i][3]);
        }
        __syncthreads();

        // O[m][dou] += sum_s P[m][s] * V[dou][s]
        #pragma unroll 8
        for (int s0 = 0; s0 < 64; s0 += 4) {
            float4 p[4], v[4];
            #pragma unroll
            for (int i = 0; i < 4; i++) p[i] = *(float4*)(Ps + (my + i) * ATS + s0);
            #pragma unroll
            for (int j = 0; j < 4; j++) v[j] = *(float4*)(Vs + (nx + j) * ATS + s0);
            #pragma unroll
            for (int i = 0; i < 4; i++)
                #pragma unroll
                for (int j = 0; j < 4; j++)
                    Oa[i][j] += p[i].x * v[j].x + p[i].y * v[j].y +
                                p[i].z * v[j].z + p[i].w * v[j].w;
        }
    }

    // Finalize: divide by l, stage transposed in Ps as [dou][m], coalesced out
    __syncthreads();
    #pragma unroll
    for (int i = 0; i < 4; i++) {
        float inv = 1.f / l_r[i];
        #pragma unroll
        for (int j = 0; j < 4; j++)
            Ps[(nx + j) * ATS + my + i] = Oa[i][j] * inv;
    }
    __syncthreads();
    float* ob = attn_out + ((size_t)b * CC + h * HD) * TT + t0;
    for (int idx = tid; idx < 64 * 16; idx += 256) {
        int dou = idx >> 4; int mq = (idx & 15) << 2;
        *(float4*)(ob + (size_t)dou * TT + mq) = *(float4*)(Ps + dou * ATS + mq);
    }
}

// ---------------------------------------------------------------------------
extern "C" void kernel_launch(void* const* d_in, const int* in_sizes, int n_in,
                              void* d_out, int out_size)
{
    const float* x       = (const float*)d_in[0];
    const float* gn_sc   = (const float*)d_in[1];
    const float* gn_bi   = (const float*)d_in[2];
    const float* qkv_w   = (const float*)d_in[3];
    const float* qkv_b   = (const float*)d_in[4];
    const float* proj_w  = (const float*)d_in[5];
    const float* proj_b  = (const float*)d_in[6];
    float* out = (float*)d_out;

    float* xn;   cudaGetSymbolAddress((void**)&xn,   g_xn);
    float* qkv;  cudaGetSymbolAddress((void**)&qkv,  g_qkv);
    float* attn; cudaGetSymbolAddress((void**)&attn, g_attn);

    const int ATTN_SMEM = 4 * 64 * ATS * sizeof(float);  // 69632 B
    cudaFuncSetAttribute(attn_kernel,
                         cudaFuncAttributeMaxDynamicSharedMemorySize, ATTN_SMEM);

    // 1) GroupNorm
    gn_kernel<<<BB * NG, 256>>>(x, gn_sc, gn_bi, xn);

    // 2) QKV GEMM: (1536x512) x (512x1024) per batch
    sgemm_kernel<<<dim3(TT / 64, M_QKV / 64, BB), 256>>>(
        qkv_w, xn, qkv_b, nullptr, qkv, M_QKV, CC, TT);

    // 3) Attention
    attn_kernel<<<dim3(TT / 64, NH, BB), 256, ATTN_SMEM>>>(qkv, attn);

    // 4) Proj GEMM + bias + residual -> out
    sgemm_kernel<<<dim3(TT / 64, CC / 64, BB), 256>>>(
        proj_w, attn, proj_b, x, out, CC, CC, TT);
}

// round 2
// speedup vs baseline: 2.0131x; 2.0131x over previous
#include <cuda_runtime.h>
#include <math.h>
#include <stdint.h>

// Problem constants
#define BB   16
#define CC   512
#define TT   1024
#define NH   8
#define HD   64
#define NG   32
#define CPG  16
#define M_QKV 1536

// Scratch
__device__ float g_xn  [(size_t)BB * CC * TT];
__device__ float g_qkv [(size_t)BB * M_QKV * TT];
__device__ float g_attn[(size_t)BB * CC * TT];

__device__ __forceinline__ uint32_t f2tf32(float x) {
    uint32_t r;
    asm("cvt.rna.tf32.f32 %0, %1;" : "=r"(r) : "f"(x));
    return r;
}
__device__ __forceinline__ float tfbits(float x) {
    return __uint_as_float(f2tf32(x));
}

__device__ __forceinline__ void mma_tf32(
    float& c0, float& c1, float& c2, float& c3,
    uint32_t a0, uint32_t a1, uint32_t a2, uint32_t a3,
    uint32_t b0, uint32_t b1)
{
    asm volatile(
        "mma.sync.aligned.m16n8k8.row.col.f32.tf32.tf32.f32 "
        "{%0,%1,%2,%3}, {%4,%5,%6,%7}, {%8,%9}, {%0,%1,%2,%3};"
        : "+f"(c0), "+f"(c1), "+f"(c2), "+f"(c3)
        : "r"(a0), "r"(a1), "r"(a2), "r"(a3), "r"(b0), "r"(b1));
}

// ---------------------------------------------------------------------------
// GroupNorm (unchanged; ~20us, memory bound)
// ---------------------------------------------------------------------------
__global__ __launch_bounds__(256) void gn_kernel(
    const float* __restrict__ x, const float* __restrict__ sc,
    const float* __restrict__ bi, float* __restrict__ xn)
{
    int b = blockIdx.x >> 5;
    int g = blockIdx.x & 31;
    const float* base  = x  + ((size_t)b * CC + g * CPG) * TT;
    float*       obase = xn + ((size_t)b * CC + g * CPG) * TT;
    int tid = threadIdx.x;

    float s = 0.f, ss = 0.f;
    for (int i = tid; i < 4096; i += 256) {
        float4 v = *(const float4*)(base + (size_t)i * 4);
        s  += v.x + v.y + v.z + v.w;
        ss += v.x * v.x + v.y * v.y + v.z * v.z + v.w * v.w;
    }
    __shared__ float rs[8], rss[8];
    #pragma unroll
    for (int off = 16; off >= 1; off >>= 1) {
        s  += __shfl_xor_sync(0xffffffffu, s,  off);
        ss += __shfl_xor_sync(0xffffffffu, ss, off);
    }
    int warp = tid >> 5, lane = tid & 31;
    if (lane == 0) { rs[warp] = s; rss[warp] = ss; }
    __syncthreads();
    if (warp == 0) {
        s  = (lane < 8) ? rs[lane]  : 0.f;
        ss = (lane < 8) ? rss[lane] : 0.f;
        #pragma unroll
        for (int off = 4; off >= 1; off >>= 1) {
            s  += __shfl_xor_sync(0xffffffffu, s,  off);
            ss += __shfl_xor_sync(0xffffffffu, ss, off);
        }
        if (lane == 0) { rs[0] = s; rss[0] = ss; }
    }
    __syncthreads();
    float mu   = rs[0] * (1.f / 16384.f);
    float var  = rss[0] * (1.f / 16384.f) - mu * mu;
    float rstd = rsqrtf(var + 1e-5f);

    for (int i = tid; i < 4096; i += 256) {
        int c    = g * CPG + (i >> 8);
        float a  = rstd * sc[c];
        float b2 = bi[c] - mu * a;
        float4 v = *(const float4*)(base + (size_t)i * 4);
        v.x = v.x * a + b2; v.y = v.y * a + b2;
        v.z = v.z * a + b2; v.w = v.w * a + b2;
        *(float4*)(obase + (size_t)i * 4) = v;
    }
}

// ---------------------------------------------------------------------------
// TF32 tensor-core GEMM: out[b][m][n] = sum_k W[m][k] X[b][k][n] + bias (+res)
// BM=128, BN=64, BK=32. 8 warps (4m x 2n), per-warp 2mt x 4nt x 4kt MMAs.
// smem holds fragments in mma register layout: A LDS.128, B LDS.64.
// ---------------------------------------------------------------------------
__global__ __launch_bounds__(256) void gemm_tc(
    const float* __restrict__ W, const float* __restrict__ X,
    const float* __restrict__ bias, const float* __restrict__ res,
    float* __restrict__ out, int M, int K, int N)
{
    __shared__ float sA[8 * 4 * 128];   // [mt][kt][lane*4+reg]
    __shared__ float sB[4 * 8 * 64];    // [kt][nt][lane*2+reg]

    int tid  = threadIdx.x;
    int wid  = tid >> 5;
    int lane = tid & 31;
    int m0 = blockIdx.y * 128, n0 = blockIdx.x * 64;
    size_t bb = blockIdx.z;
    const float* Xb   = X   + bb * (size_t)K * N;
    float*       outb = out + bb * (size_t)M * N;

    int warp_m = wid >> 1, warp_n = wid & 1;
    int mt0 = warp_m * 2, nt0 = warp_n * 4;

    float acc[2][4][4] = {};

    for (int k0 = 0; k0 < K; k0 += 32) {
        // ---- produce A fragments ----
        #pragma unroll
        for (int i = 0; i < 4; i++) {
            int f   = tid + i * 256;          // 1024 float4s
            int row = f >> 3;
            int kq  = (f & 7) << 2;
            float4 v = *(const float4*)(W + (size_t)(m0 + row) * K + k0 + kq);
            float vv[4] = {v.x, v.y, v.z, v.w};
            int mt = row >> 4, r = row & 15;
            #pragma unroll
            for (int j = 0; j < 4; j++) {
                int k = kq + j;
                int kt = k >> 3, c = k & 7;
                int ln = ((r & 7) << 2) | (c & 3);
                int rg = (r >> 3) | (((c >> 2) & 1) << 1);
                sA[((mt * 4 + kt) << 7) + (ln << 2) + rg] = tfbits(vv[j]);
            }
        }
        // ---- produce B fragments ----
        #pragma unroll
        for (int i = 0; i < 2; i++) {
            int f  = tid + i * 256;           // 512 float4s
            int k  = f >> 4;
            int nq = (f & 15) << 2;
            float4 v = *(const float4*)(Xb + (size_t)(k0 + k) * N + n0 + nq);
            float vv[4] = {v.x, v.y, v.z, v.w};
            int kt = k >> 3, c = k & 7;
            #pragma unroll
            for (int j = 0; j < 4; j++) {
                int n = nq + j;
                int nt = n >> 3;
                int ln = ((n & 7) << 2) | (c & 3);
                int rg = (c >> 2) & 1;
                sB[((kt * 8 + nt) << 6) + (ln << 1) + rg] = tfbits(vv[j]);
            }
        }
        __syncthreads();

        #pragma unroll
        for (int kt = 0; kt < 4; kt++) {
            uint4 a[2];
            #pragma unroll
            for (int im = 0; im < 2; im++)
                a[im] = *(const uint4*)&sA[(((mt0 + im) * 4 + kt) << 7) + (lane << 2)];
            uint2 b[4];
            #pragma unroll
            for (int in = 0; in < 4; in++)
                b[in] = *(const uint2*)&sB[((kt * 8 + nt0 + in) << 6) + (lane << 1)];
            #pragma unroll
            for (int im = 0; im < 2; im++)
                #pragma unroll
                for (int in = 0; in < 4; in++)
                    mma_tf32(acc[im][in][0], acc[im][in][1],
                             acc[im][in][2], acc[im][in][3],
                             a[im].x, a[im].y, a[im].z, a[im].w,
                             b[in].x, b[in].y);
        }
        __syncthreads();
    }

    // epilogue
    int group = lane >> 2, tig = lane & 3;
    #pragma unroll
    for (int im = 0; im < 2; im++) {
        int mbase = m0 + (mt0 + im) * 16;
        float bv0 = bias[mbase + group];
        float bv1 = bias[mbase + group + 8];
        #pragma unroll
        for (int in = 0; in < 4; in++) {
            int n = n0 + (nt0 + in) * 8 + tig * 2;
            size_t o0 = (size_t)(mbase + group) * N + n;
            size_t o1 = (size_t)(mbase + group + 8) * N + n;
            float2 r0 = make_float2(acc[im][in][0] + bv0, acc[im][in][1] + bv0);
            float2 r1 = make_float2(acc[im][in][2] + bv1, acc[im][in][3] + bv1);
            if (res) {
                const float* rb = res + bb * (size_t)M * N;
                float2 x0 = *(const float2*)(rb + o0);
                float2 x1 = *(const float2*)(rb + o1);
                r0.x += x0.x; r0.y += x0.y; r1.x += x1.x; r1.y += x1.y;
            }
            *(float2*)(outb + o0) = r0;
            *(float2*)(outb + o1) = r1;
        }
    }
}

// ---------------------------------------------------------------------------
// Flash attention on tensor cores (tf32). Block: 128 queries x full keys.
// 8 warps, each owns one 16-query m-tile for BOTH QK^T and PV.
// qkv layout: [b][o][t], o = s*512 + h*64 + d
// ---------------------------------------------------------------------------
__global__ __launch_bounds__(256) void attn_tc(
    const float* __restrict__ qkv, float* __restrict__ attn_out)
{
    extern __shared__ float sm[];
    float* sQ = sm;                 // [mt8][kt8][128]  (32KB)
    float* sK = sm + 8192;          // [kt8][nt8][64]   (16KB)
    float* sV = sm + 12288;         // [kt8][nt8][64]   (16KB)
    float* sO = sm;                 // reuse: [d64][stride 132]

    int t0 = blockIdx.x * 128;
    int h  = blockIdx.y;
    int b  = blockIdx.z;
    const float* qb = qkv + ((size_t)b * M_QKV + h * HD) * TT;
    const float* kb = qb + (size_t)CC * TT;
    const float* vb = qb + (size_t)2 * CC * TT;

    int tid  = threadIdx.x;
    int wid  = tid >> 5;
    int lane = tid & 31;
    int group = lane >> 2, tig = lane & 3;

    // ---- load Q tile (scaled by 1/8) into fragment smem ----
    #pragma unroll
    for (int i = 0; i < 8; i++) {
        int f  = tid + i * 256;           // 2048 float4s: 128 t x 64 d
        int d  = f >> 5;
        int tq = (f & 31) << 2;
        float4 v = *(const float4*)(qb + (size_t)d * TT + t0 + tq);
        float vv[4] = {v.x * 0.125f, v.y * 0.125f, v.z * 0.125f, v.w * 0.125f};
        int kt = d >> 3, c = d & 7;
        #pragma unroll
        for (int j = 0; j < 4; j++) {
            int m = tq + j;
            int mt = m >> 4, r = m & 15;
            int ln = ((r & 7) << 2) | (c & 3);
            int rg = (r >> 3) | (((c >> 2) & 1) << 1);
            sQ[((mt * 8 + kt) << 7) + (ln << 2) + rg] = tfbits(vv[j]);
        }
    }
    __syncthreads();

    // hoist this warp's Q fragments to registers (mt = wid)
    uint4 qa[8];
    #pragma unroll
    for (int kt = 0; kt < 8; kt++)
        qa[kt] = *(const uint4*)&sQ[((wid * 8 + kt) << 7) + (lane << 2)];

    float o[8][4] = {};
    float m0r = -1e30f, m1r = -1e30f, l0r = 0.f, l1r = 0.f;

    for (int c0 = 0; c0 < TT; c0 += 64) {
        __syncthreads();
        // ---- load K chunk: element (k=d, n=key) ----
        #pragma unroll
        for (int i = 0; i < 4; i++) {
            int f  = tid + i * 256;       // 1024 f4: 64 d x 64 t
            int d  = f >> 4;
            int tq = (f & 15) << 2;
            float4 v = *(const float4*)(kb + (size_t)d * TT + c0 + tq);
            float vv[4] = {v.x, v.y, v.z, v.w};
            int kt = d >> 3;
            #pragma unroll
            for (int j = 0; j < 4; j++) {
                int n = tq + j;
                int nt = n >> 3;
                int ln = ((n & 7) << 2) | (d & 3);
                int rg = (d >> 2) & 1;
                sK[((kt * 8 + nt) << 6) + (ln << 1) + rg] = tfbits(vv[j]);
            }
        }
        // ---- load V chunk: element (k=key, n=d) ----
        #pragma unroll
        for (int i = 0; i < 4; i++) {
            int f  = tid + i * 256;
            int d  = f >> 4;
            int tq = (f & 15) << 2;
            float4 v = *(const float4*)(vb + (size_t)d * TT + c0 + tq);
            float vv[4] = {v.x, v.y, v.z, v.w};
            int nt = d >> 3;
            #pragma unroll
            for (int j = 0; j < 4; j++) {
                int key = tq + j;
                int kt = key >> 3;
                int ln = ((d & 7) << 2) | (key & 3);
                int rg = (key >> 2) & 1;
                sV[((kt * 8 + nt) << 6) + (ln << 1) + rg] = tfbits(vv[j]);
            }
        }
        __syncthreads();

        // ---- S = Q K^T : 8 nt x 8 kt MMAs ----
        float s[8][4] = {};
        #pragma unroll
        for (int kt = 0; kt < 8; kt++) {
            #pragma unroll
            for (int nt = 0; nt < 8; nt++) {
                uint2 bf = *(const uint2*)&sK[((kt * 8 + nt) << 6) + (lane << 1)];
                mma_tf32(s[nt][0], s[nt][1], s[nt][2], s[nt][3],
                         qa[kt].x, qa[kt].y, qa[kt].z, qa[kt].w, bf.x, bf.y);
            }
        }

        // ---- online softmax (rows: group, group+8) ----
        float mx0 = -1e30f, mx1 = -1e30f;
        #pragma unroll
        for (int nt = 0; nt < 8; nt++) {
            mx0 = fmaxf(mx0, fmaxf(s[nt][0], s[nt][1]));
            mx1 = fmaxf(mx1, fmaxf(s[nt][2], s[nt][3]));
        }
        mx0 = fmaxf(mx0, __shfl_xor_sync(0xffffffffu, mx0, 1));
        mx0 = fmaxf(mx0, __shfl_xor_sync(0xffffffffu, mx0, 2));
        mx1 = fmaxf(mx1, __shfl_xor_sync(0xffffffffu, mx1, 1));
        mx1 = fmaxf(mx1, __shfl_xor_sync(0xffffffffu, mx1, 2));
        float nm0 = fmaxf(m0r, mx0), nm1 = fmaxf(m1r, mx1);
        float cr0 = __expf(m0r - nm0), cr1 = __expf(m1r - nm1);
        m0r = nm0; m1r = nm1;
        float sum0 = 0.f, sum1 = 0.f;
        #pragma unroll
        for (int nt = 0; nt < 8; nt++) {
            s[nt][0] = __expf(s[nt][0] - nm0);
            s[nt][1] = __expf(s[nt][1] - nm0);
            s[nt][2] = __expf(s[nt][2] - nm1);
            s[nt][3] = __expf(s[nt][3] - nm1);
            sum0 += s[nt][0] + s[nt][1];
            sum1 += s[nt][2] + s[nt][3];
        }
        sum0 += __shfl_xor_sync(0xffffffffu, sum0, 1);
        sum0 += __shfl_xor_sync(0xffffffffu, sum0, 2);
        sum1 += __shfl_xor_sync(0xffffffffu, sum1, 1);
        sum1 += __shfl_xor_sync(0xffffffffu, sum1, 2);
        l0r = l0r * cr0 + sum0;
        l1r = l1r * cr1 + sum1;
        #pragma unroll
        for (int nt = 0; nt < 8; nt++) {
            o[nt][0] *= cr0; o[nt][1] *= cr0;
            o[nt][2] *= cr1; o[nt][3] *= cr1;
        }

        // ---- O += P V : remap P (C-layout -> A-layout) via shuffles ----
        int src1 = (lane & ~3) | (tig >> 1);
        int src2 = src1 + 2;
        #pragma unroll
        for (int kt = 0; kt < 8; kt++) {
            float v00 = __shfl_sync(0xffffffffu, s[kt][0], src1);
            float v01 = __shfl_sync(0xffffffffu, s[kt][1], src1);
            float v02 = __shfl_sync(0xffffffffu, s[kt][0], src2);
            float v03 = __shfl_sync(0xffffffffu, s[kt][1], src2);
            float v10 = __shfl_sync(0xffffffffu, s[kt][2], src1);
            float v11 = __shfl_sync(0xffffffffu, s[kt][3], src1);
            float v12 = __shfl_sync(0xffffffffu, s[kt][2], src2);
            float v13 = __shfl_sync(0xffffffffu, s[kt][3], src2);
            bool odd = (tig & 1);
            uint32_t a0 = f2tf32(odd ? v01 : v00);
            uint32_t a2 = f2tf32(odd ? v03 : v02);
            uint32_t a1 = f2tf32(odd ? v11 : v10);
            uint32_t a3 = f2tf32(odd ? v13 : v12);
            #pragma unroll
            for (int nt = 0; nt < 8; nt++) {
                uint2 bf = *(const uint2*)&sV[((kt * 8 + nt) << 6) + (lane << 1)];
                mma_tf32(o[nt][0], o[nt][1], o[nt][2], o[nt][3],
                         a0, a1, a2, a3, bf.x, bf.y);
            }
        }
    }

    // ---- finalize: stage transposed in smem, coalesced write ----
    __syncthreads();   // everyone done reading sK/sV before sO overwrite
    float inv0 = 1.f / l0r, inv1 = 1.f / l1r;
    int q0 = wid * 16 + group;
    #pragma unroll
    for (int nt = 0; nt < 8; nt++) {
        int col = nt * 8 + tig * 2;
        sO[(col)     * 132 + q0]     = o[nt][0] * inv0;
        sO[(col + 1) * 132 + q0]     = o[nt][1] * inv0;
        sO[(col)     * 132 + q0 + 8] = o[nt][2] * inv1;
        sO[(col + 1) * 132 + q0 + 8] = o[nt][3] * inv1;
    }
    __syncthreads();
    float* ob = attn_out + ((size_t)b * CC + h * HD) * TT + t0;
    for (int idx = tid; idx < 64 * 32; idx += 256) {
        int d = idx >> 5, q4 = (idx & 31) << 2;
        *(float4*)(ob + (size_t)d * TT + q4) = *(const float4*)(sO + d * 132 + q4);
    }
}

// ---------------------------------------------------------------------------
extern "C" void kernel_launch(void* const* d_in, const int* in_sizes, int n_in,
                              void* d_out, int out_size)
{
    const float* x       = (const float*)d_in[0];
    const float* gn_sc   = (const float*)d_in[1];
    const float* gn_bi   = (const float*)d_in[2];
    const float* qkv_w   = (const float*)d_in[3];
    const float* qkv_b   = (const float*)d_in[4];
    const float* proj_w  = (const float*)d_in[5];
    const float* proj_b  = (const float*)d_in[6];
    float* out = (float*)d_out;

    float* xn;   cudaGetSymbolAddress((void**)&xn,   g_xn);
    float* qkv;  cudaGetSymbolAddress((void**)&qkv,  g_qkv);
    float* attn; cudaGetSymbolAddress((void**)&attn, g_attn);

    const int ATTN_SMEM = 65536;
    cudaFuncSetAttribute(attn_tc,
                         cudaFuncAttributeMaxDynamicSharedMemorySize, ATTN_SMEM);

    gn_kernel<<<BB * NG, 256>>>(x, gn_sc, gn_bi, xn);

    gemm_tc<<<dim3(TT / 64, M_QKV / 128, BB), 256>>>(
        qkv_w, xn, qkv_b, nullptr, qkv, M_QKV, CC, TT);

    attn_tc<<<dim3(TT / 128, NH, BB), 256, ATTN_SMEM>>>(qkv, attn);

    gemm_tc<<<dim3(TT / 64, CC / 128, BB), 256>>>(
        proj_w, attn, proj_b, x, out, CC, CC, TT);
}

// round 3
// speedup vs baseline: 4.1767x; 2.0748x over previous
#include <cuda_runtime.h>
#include <cuda_fp16.h>
#include <math.h>
#include <stdint.h>

// Problem constants
#define BB   16
#define CC   512
#define TT   1024
#define NH   8
#define HD   64
#define NG   32
#define CPG  16
#define M_QKV 1536

// Scratch
__device__ float g_xn  [(size_t)BB * CC * TT];
__device__ float g_qkv [(size_t)BB * M_QKV * TT];
__device__ float g_attn[(size_t)BB * CC * TT];

// pack two floats -> f16x2 (lo in low half)
__device__ __forceinline__ uint32_t h2(float lo, float hi) {
    uint32_t u;
    asm("cvt.rn.f16x2.f32 %0, %2, %1;" : "=r"(u) : "f"(lo), "f"(hi));
    return u;
}

__device__ __forceinline__ void mma_f16(
    float& c0, float& c1, float& c2, float& c3,
    uint32_t a0, uint32_t a1, uint32_t a2, uint32_t a3,
    uint32_t b0, uint32_t b1)
{
    asm volatile(
        "mma.sync.aligned.m16n8k16.row.col.f32.f16.f16.f32 "
        "{%0,%1,%2,%3}, {%4,%5,%6,%7}, {%8,%9}, {%0,%1,%2,%3};"
        : "+f"(c0), "+f"(c1), "+f"(c2), "+f"(c3)
        : "r"(a0), "r"(a1), "r"(a2), "r"(a3), "r"(b0), "r"(b1));
}

// ---------------------------------------------------------------------------
// GroupNorm (memory bound, ~20us)
// ---------------------------------------------------------------------------
__global__ __launch_bounds__(256) void gn_kernel(
    const float* __restrict__ x, const float* __restrict__ sc,
    const float* __restrict__ bi, float* __restrict__ xn)
{
    int b = blockIdx.x >> 5;
    int g = blockIdx.x & 31;
    const float* base  = x  + ((size_t)b * CC + g * CPG) * TT;
    float*       obase = xn + ((size_t)b * CC + g * CPG) * TT;
    int tid = threadIdx.x;

    float s = 0.f, ss = 0.f;
    for (int i = tid; i < 4096; i += 256) {
        float4 v = *(const float4*)(base + (size_t)i * 4);
        s  += v.x + v.y + v.z + v.w;
        ss += v.x * v.x + v.y * v.y + v.z * v.z + v.w * v.w;
    }
    __shared__ float rs[8], rss[8];
    #pragma unroll
    for (int off = 16; off >= 1; off >>= 1) {
        s  += __shfl_xor_sync(0xffffffffu, s,  off);
        ss += __shfl_xor_sync(0xffffffffu, ss, off);
    }
    int warp = tid >> 5, lane = tid & 31;
    if (lane == 0) { rs[warp] = s; rss[warp] = ss; }
    __syncthreads();
    if (warp == 0) {
        s  = (lane < 8) ? rs[lane]  : 0.f;
        ss = (lane < 8) ? rss[lane] : 0.f;
        #pragma unroll
        for (int off = 4; off >= 1; off >>= 1) {
            s  += __shfl_xor_sync(0xffffffffu, s,  off);
            ss += __shfl_xor_sync(0xffffffffu, ss, off);
        }
        if (lane == 0) { rs[0] = s; rss[0] = ss; }
    }
    __syncthreads();
    float mu   = rs[0] * (1.f / 16384.f);
    float var  = rss[0] * (1.f / 16384.f) - mu * mu;
    float rstd = rsqrtf(var + 1e-5f);

    for (int i = tid; i < 4096; i += 256) {
        int c    = g * CPG + (i >> 8);
        float a  = rstd * sc[c];
        float b2 = bi[c] - mu * a;
        float4 v = *(const float4*)(base + (size_t)i * 4);
        v.x = v.x * a + b2; v.y = v.y * a + b2;
        v.z = v.z * a + b2; v.w = v.w * a + b2;
        *(float4*)(obase + (size_t)i * 4) = v;
    }
}

// ---------------------------------------------------------------------------
// FP16 tensor-core GEMM: out[b][m][n] = sum_k W[m][k] X[b][k][n] + bias (+res)
// BM=128, BN=64, BK=64. 8 warps (4m x 2n), per-warp 2mt x 4nt, kt-loop 4.
// smem holds m16n8k16 fragments: A frag = uint4/lane, B frag = uint2/lane.
// ---------------------------------------------------------------------------
__global__ __launch_bounds__(256) void gemm_tc(
    const float* __restrict__ W, const float* __restrict__ X,
    const float* __restrict__ bias, const float* __restrict__ res,
    float* __restrict__ out, int M, int K, int N)
{
    __shared__ uint32_t sA[8 * 4 * 128];   // [mt][kt][lane*4+reg]  16KB
    __shared__ uint32_t sB[4 * 8 * 64];    // [kt][nt][lane*2+reg]   8KB

    int tid  = threadIdx.x;
    int wid  = tid >> 5;
    int lane = tid & 31;
    int m0 = blockIdx.y * 128, n0 = blockIdx.x * 64;
    size_t bb = blockIdx.z;
    const float* Xb   = X   + bb * (size_t)K * N;
    float*       outb = out + bb * (size_t)M * N;

    int warp_m = wid >> 1, warp_n = wid & 1;
    int mt0 = warp_m * 2, nt0 = warp_n * 4;

    float acc[2][4][4] = {};

    for (int k0 = 0; k0 < K; k0 += 64) {
        // ---- produce A fragments: 128 rows x 64 k ----
        #pragma unroll
        for (int i = 0; i < 8; i++) {
            int f   = tid + i * 256;            // 2048 float4s
            int row = f >> 4;
            int kq  = (f & 15) << 2;
            float4 v = *(const float4*)(W + (size_t)(m0 + row) * K + k0 + kq);
            int mt = row >> 4, g = row & 7;
            int kt = kq >> 4;
            int r  = ((row >> 3) & 1) | (((kq >> 3) & 1) << 1);
            int t0i = (kq & 7) >> 1;
            uint32_t* base = &sA[((mt * 4 + kt) << 7) + ((g * 4 + t0i) << 2) + r];
            base[0] = h2(v.x, v.y);
            base[4] = h2(v.z, v.w);
        }
        // ---- produce B fragments: 64 k x 64 n (load k-row pairs) ----
        #pragma unroll
        for (int i = 0; i < 2; i++) {
            int f  = tid + i * 256;             // 512 items
            int kp = f >> 4;                    // k-pair index 0..31
            int nq = (f & 15) << 2;
            const float* p0 = Xb + (size_t)(k0 + 2 * kp) * N + n0 + nq;
            float4 x0 = *(const float4*)p0;
            float4 x1 = *(const float4*)(p0 + N);
            int t  = kp & 3;
            int r  = (kp >> 2) & 1;
            int kt = kp >> 3;
            int nt = nq >> 3;
            int lb = ((nq & 7) * 4 + t) * 2 + r;
            uint32_t* base = &sB[((kt * 8 + nt) << 6) + lb];
            base[0] = h2(x0.x, x1.x);
            base[8] = h2(x0.y, x1.y);
            base[16] = h2(x0.z, x1.z);
            base[24] = h2(x0.w, x1.w);
        }
        __syncthreads();

        #pragma unroll
        for (int kt = 0; kt < 4; kt++) {
            uint4 a[2];
            #pragma unroll
            for (int im = 0; im < 2; im++)
                a[im] = *(const uint4*)&sA[(((mt0 + im) * 4 + kt) << 7) + (lane << 2)];
            uint2 b[4];
            #pragma unroll
            for (int in = 0; in < 4; in++)
                b[in] = *(const uint2*)&sB[((kt * 8 + nt0 + in) << 6) + (lane << 1)];
            #pragma unroll
            for (int im = 0; im < 2; im++)
                #pragma unroll
                for (int in = 0; in < 4; in++)
                    mma_f16(acc[im][in][0], acc[im][in][1],
                            acc[im][in][2], acc[im][in][3],
                            a[im].x, a[im].y, a[im].z, a[im].w,
                            b[in].x, b[in].y);
        }
        __syncthreads();
    }

    // epilogue
    int group = lane >> 2, tig = lane & 3;
    #pragma unroll
    for (int im = 0; im < 2; im++) {
        int mbase = m0 + (mt0 + im) * 16;
        float bv0 = bias[mbase + group];
        float bv1 = bias[mbase + group + 8];
        #pragma unroll
        for (int in = 0; in < 4; in++) {
            int n = n0 + (nt0 + in) * 8 + tig * 2;
            size_t o0 = (size_t)(mbase + group) * N + n;
            size_t o1 = (size_t)(mbase + group + 8) * N + n;
            float2 r0 = make_float2(acc[im][in][0] + bv0, acc[im][in][1] + bv0);
            float2 r1 = make_float2(acc[im][in][2] + bv1, acc[im][in][3] + bv1);
            if (res) {
                const float* rb = res + bb * (size_t)M * N;
                float2 x0 = *(const float2*)(rb + o0);
                float2 x1 = *(const float2*)(rb + o1);
                r0.x += x0.x; r0.y += x0.y; r1.x += x1.x; r1.y += x1.y;
            }
            *(float2*)(outb + o0) = r0;
            *(float2*)(outb + o1) = r1;
        }
    }
}

// ---------------------------------------------------------------------------
// Flash attention, fp16 MMA. Block: 128 queries x all 1024 keys, 8 warps.
// qkv layout: [b][o][t], o = s*512 + h*64 + d
// ---------------------------------------------------------------------------
__global__ __launch_bounds__(256) void attn_tc(
    const float* __restrict__ qkv, float* __restrict__ attn_out)
{
    __shared__ uint32_t sm_u[8448];        // 33792 B
    uint32_t* sQ = sm_u;                   // [mt8][kt4][128]  4096
    uint32_t* sK = sm_u + 4096;            // [kt4][nt8][64]   2048
    uint32_t* sV = sm_u + 6144;            // [kt4][nt8][64]   2048
    float*    sO = (float*)sm_u;           // [d64][stride132]

    int t0 = blockIdx.x * 128;
    int h  = blockIdx.y;
    int b  = blockIdx.z;
    const float* qb = qkv + ((size_t)b * M_QKV + h * HD) * TT;
    const float* kb = qb + (size_t)CC * TT;
    const float* vb = qb + (size_t)2 * CC * TT;

    int tid  = threadIdx.x;
    int wid  = tid >> 5;
    int lane = tid & 31;
    int group = lane >> 2, tig = lane & 3;

    // ---- load Q tile (scaled), pack A fragments (d-pair rows) ----
    #pragma unroll
    for (int i = 0; i < 4; i++) {
        int f  = tid + i * 256;            // 1024 items
        int dp = f >> 5;                   // d-pair 0..31
        int mq = (f & 31) << 2;
        const float* p0 = qb + (size_t)(2 * dp) * TT + t0 + mq;
        float4 x0 = *(const float4*)p0;
        float4 x1 = *(const float4*)(p0 + TT);
        float a0[4] = {x0.x, x0.y, x0.z, x0.w};
        float a1[4] = {x1.x, x1.y, x1.z, x1.w};
        int t  = dp & 3;
        int kh = (dp >> 2) & 1;
        int kt = dp >> 3;
        #pragma unroll
        for (int j = 0; j < 4; j++) {
            int m = mq + j;
            int mt = m >> 4, g = m & 7;
            int r = ((m >> 3) & 1) | (kh << 1);
            sQ[((mt * 4 + kt) << 7) + ((g * 4 + t) << 2) + r] =
                h2(a0[j] * 0.125f, a1[j] * 0.125f);
        }
    }
    __syncthreads();

    // hoist this warp's Q fragments (mt = wid)
    uint4 qa[4];
    #pragma unroll
    for (int kt = 0; kt < 4; kt++)
        qa[kt] = *(const uint4*)&sQ[((wid * 4 + kt) << 7) + (lane << 2)];

    float o[8][4] = {};
    float m0r = -1e30f, m1r = -1e30f, l0r = 0.f, l1r = 0.f;

    for (int c0 = 0; c0 < TT; c0 += 64) {
        __syncthreads();
        // ---- K chunk: B-frag (k=d, n=key); load d-pair rows ----
        #pragma unroll
        for (int i = 0; i < 2; i++) {
            int f  = tid + i * 256;        // 512 items
            int dp = f >> 4;               // d-pair 0..31
            int tq = (f & 15) << 2;
            const float* p0 = kb + (size_t)(2 * dp) * TT + c0 + tq;
            float4 x0 = *(const float4*)p0;
            float4 x1 = *(const float4*)(p0 + TT);
            int t  = dp & 3;
            int r  = (dp >> 2) & 1;
            int kt = dp >> 3;
            int nt = tq >> 3;
            uint32_t* base = &sK[((kt * 8 + nt) << 6) + ((tq & 7) * 4 + t) * 2 + r];
            base[0]  = h2(x0.x, x1.x);
            base[8]  = h2(x0.y, x1.y);
            base[16] = h2(x0.z, x1.z);
            base[24] = h2(x0.w, x1.w);
        }
        // ---- V chunk: B-frag (k=key, n=d); key pairs within float4 ----
        #pragma unroll
        for (int i = 0; i < 4; i++) {
            int f  = tid + i * 256;        // 1024 f4
            int d  = f >> 4;
            int tq = (f & 15) << 2;
            float4 v = *(const float4*)(vb + (size_t)d * TT + c0 + tq);
            int kt = tq >> 4;
            int kh = (tq >> 3) & 1;
            int t0i = (tq & 7) >> 1;
            int nt = d >> 3;
            uint32_t* base = &sV[((kt * 8 + nt) << 6) + ((d & 7) * 4 + t0i) * 2 + kh];
            base[0] = h2(v.x, v.y);
            base[2] = h2(v.z, v.w);
        }
        __syncthreads();

        // ---- S = Q K^T : 4 kt x 8 nt MMAs ----
        float s[8][4] = {};
        #pragma unroll
        for (int kt = 0; kt < 4; kt++) {
            #pragma unroll
            for (int nt = 0; nt < 8; nt++) {
                uint2 bf = *(const uint2*)&sK[((kt * 8 + nt) << 6) + (lane << 1)];
                mma_f16(s[nt][0], s[nt][1], s[nt][2], s[nt][3],
                        qa[kt].x, qa[kt].y, qa[kt].z, qa[kt].w, bf.x, bf.y);
            }
        }

        // ---- online softmax (rows: group, group+8) ----
        float mx0 = -1e30f, mx1 = -1e30f;
        #pragma unroll
        for (int nt = 0; nt < 8; nt++) {
            mx0 = fmaxf(mx0, fmaxf(s[nt][0], s[nt][1]));
            mx1 = fmaxf(mx1, fmaxf(s[nt][2], s[nt][3]));
        }
        mx0 = fmaxf(mx0, __shfl_xor_sync(0xffffffffu, mx0, 1));
        mx0 = fmaxf(mx0, __shfl_xor_sync(0xffffffffu, mx0, 2));
        mx1 = fmaxf(mx1, __shfl_xor_sync(0xffffffffu, mx1, 1));
        mx1 = fmaxf(mx1, __shfl_xor_sync(0xffffffffu, mx1, 2));
        float nm0 = fmaxf(m0r, mx0), nm1 = fmaxf(m1r, mx1);
        float cr0 = __expf(m0r - nm0), cr1 = __expf(m1r - nm1);
        m0r = nm0; m1r = nm1;
        float sum0 = 0.f, sum1 = 0.f;
        #pragma unroll
        for (int nt = 0; nt < 8; nt++) {
            s[nt][0] = __expf(s[nt][0] - nm0);
            s[nt][1] = __expf(s[nt][1] - nm0);
            s[nt][2] = __expf(s[nt][2] - nm1);
            s[nt][3] = __expf(s[nt][3] - nm1);
            sum0 += s[nt][0] + s[nt][1];
            sum1 += s[nt][2] + s[nt][3];
        }
        sum0 += __shfl_xor_sync(0xffffffffu, sum0, 1);
        sum0 += __shfl_xor_sync(0xffffffffu, sum0, 2);
        sum1 += __shfl_xor_sync(0xffffffffu, sum1, 1);
        sum1 += __shfl_xor_sync(0xffffffffu, sum1, 2);
        l0r = l0r * cr0 + sum0;
        l1r = l1r * cr1 + sum1;
        #pragma unroll
        for (int nt = 0; nt < 8; nt++) {
            o[nt][0] *= cr0; o[nt][1] *= cr0;
            o[nt][2] *= cr1; o[nt][3] *= cr1;
        }

        // ---- O += P V : C-fragment maps directly onto A-fragment ----
        #pragma unroll
        for (int kt = 0; kt < 4; kt++) {
            uint32_t a0 = h2(s[2 * kt][0],     s[2 * kt][1]);
            uint32_t a1 = h2(s[2 * kt][2],     s[2 * kt][3]);
            uint32_t a2 = h2(s[2 * kt + 1][0], s[2 * kt + 1][1]);
            uint32_t a3 = h2(s[2 * kt + 1][2], s[2 * kt + 1][3]);
            #pragma unroll
            for (int nt = 0; nt < 8; nt++) {
                uint2 bf = *(const uint2*)&sV[((kt * 8 + nt) << 6) + (lane << 1)];
                mma_f16(o[nt][0], o[nt][1], o[nt][2], o[nt][3],
                        a0, a1, a2, a3, bf.x, bf.y);
            }
        }
    }

    // ---- finalize: stage transposed in smem, coalesced write ----
    __syncthreads();
    float inv0 = 1.f / l0r, inv1 = 1.f / l1r;
    int q0 = wid * 16 + group;
    #pragma unroll
    for (int nt = 0; nt < 8; nt++) {
        int col = nt * 8 + tig * 2;
        sO[(col)     * 132 + q0]     = o[nt][0] * inv0;
        sO[(col + 1) * 132 + q0]     = o[nt][1] * inv0;
        sO[(col)     * 132 + q0 + 8] = o[nt][2] * inv1;
        sO[(col + 1) * 132 + q0 + 8] = o[nt][3] * inv1;
    }
    __syncthreads();
    float* ob = attn_out + ((size_t)b * CC + h * HD) * TT + t0;
    for (int idx = tid; idx < 64 * 32; idx += 256) {
        int d = idx >> 5, q4 = (idx & 31) << 2;
        *(float4*)(ob + (size_t)d * TT + q4) = *(const float4*)(sO + d * 132 + q4);
    }
}

// ---------------------------------------------------------------------------
extern "C" void kernel_launch(void* const* d_in, const int* in_sizes, int n_in,
                              void* d_out, int out_size)
{
    const float* x       = (const float*)d_in[0];
    const float* gn_sc   = (const float*)d_in[1];
    const float* gn_bi   = (const float*)d_in[2];
    const float* qkv_w   = (const float*)d_in[3];
    const float* qkv_b   = (const float*)d_in[4];
    const float* proj_w  = (const float*)d_in[5];
    const float* proj_b  = (const float*)d_in[6];
    float* out = (float*)d_out;

    float* xn;   cudaGetSymbolAddress((void**)&xn,   g_xn);
    float* qkv;  cudaGetSymbolAddress((void**)&qkv,  g_qkv);
    float* attn; cudaGetSymbolAddress((void**)&attn, g_attn);

    gn_kernel<<<BB * NG, 256>>>(x, gn_sc, gn_bi, xn);

    gemm_tc<<<dim3(TT / 64, M_QKV / 128, BB), 256>>>(
        qkv_w, xn, qkv_b, nullptr, qkv, M_QKV, CC, TT);

    attn_tc<<<dim3(TT / 128, NH, BB), 256>>>(qkv, attn);

    gemm_tc<<<dim3(TT / 64, CC / 128, BB), 256>>>(
        proj_w, attn, proj_b, x, out, CC, CC, TT);
}

// round 5
// speedup vs baseline: 7.0061x; 1.6774x over previous
#include <cuda_runtime.h>
#include <cuda_fp16.h>
#include <math.h>
#include <stdint.h>

// Problem constants
#define BB   16
#define CC   512
#define TT   1024
#define NH   8
#define HD   64
#define NG   32
#define CPG  16
#define M_QKV 1536

// Scratch (fp16)
__device__ __half g_wq   [(size_t)M_QKV * CC];
__device__ __half g_wp   [(size_t)CC * CC];
__device__ __half g_xnT  [(size_t)BB * TT * CC];    // [b][t][c]
__device__ __half g_qkvh [(size_t)BB * M_QKV * TT]; // [b][o][t]
__device__ __half g_attnT[(size_t)BB * TT * CC];    // [b][t][c]

// ---------------------------------------------------------------------------
// helpers
// ---------------------------------------------------------------------------
__device__ __forceinline__ uint32_t h2(float lo, float hi) {
    uint32_t u;
    asm("cvt.rn.f16x2.f32 %0, %2, %1;" : "=r"(u) : "f"(lo), "f"(hi));
    return u;
}
__device__ __forceinline__ uint32_t hmul2u(uint32_t a, uint32_t b) {
    uint32_t r;
    asm("mul.rn.f16x2 %0, %1, %2;" : "=r"(r) : "r"(a), "r"(b));
    return r;
}
__device__ __forceinline__ uint32_t smem_u32(const void* p) {
    uint32_t a;
    asm("{ .reg .u64 t; cvta.to.shared.u64 t, %1; cvt.u32.u64 %0, t; }"
        : "=r"(a) : "l"(p));
    return a;
}
__device__ __forceinline__ void cp16(uint32_t s, const void* g) {
    asm volatile("cp.async.cg.shared.global [%0], [%1], 16;"
                 :: "r"(s), "l"(g) : "memory");
}
__device__ __forceinline__ void cp_commit() {
    asm volatile("cp.async.commit_group;" ::: "memory");
}
template<int W>
__device__ __forceinline__ void cp_wait() {
    asm volatile("cp.async.wait_group %0;" :: "n"(W) : "memory");
}
__device__ __forceinline__ uint4 ldsm4(uint32_t a) {
    uint4 r;
    asm volatile("ldmatrix.sync.aligned.m8n8.x4.shared.b16 {%0,%1,%2,%3}, [%4];"
                 : "=r"(r.x), "=r"(r.y), "=r"(r.z), "=r"(r.w) : "r"(a));
    return r;
}
__device__ __forceinline__ uint32_t swz(uint32_t b) { return b ^ ((b >> 3) & 0x70); }

__device__ __forceinline__ void mma_f16(
    float& c0, float& c1, float& c2, float& c3,
    uint32_t a0, uint32_t a1, uint32_t a2, uint32_t a3,
    uint32_t b0, uint32_t b1)
{
    asm volatile(
        "mma.sync.aligned.m16n8k16.row.col.f32.f16.f16.f32 "
        "{%0,%1,%2,%3}, {%4,%5,%6,%7}, {%8,%9}, {%0,%1,%2,%3};"
        : "+f"(c0), "+f"(c1), "+f"(c2), "+f"(c3)
        : "r"(a0), "r"(a1), "r"(a2), "r"(a3), "r"(b0), "r"(b1));
}

// ---------------------------------------------------------------------------
// fp32 -> fp16 weight conversion
// ---------------------------------------------------------------------------
__global__ __launch_bounds__(256) void cvt_kernel(
    const float* __restrict__ in, __half* __restrict__ out, int n8)
{
    int i = blockIdx.x * 256 + threadIdx.x;
    if (i >= n8) return;
    float4 a = *(const float4*)(in + (size_t)i * 8);
    float4 b = *(const float4*)(in + (size_t)i * 8 + 4);
    uint4 o;
    o.x = h2(a.x, a.y); o.y = h2(a.z, a.w);
    o.z = h2(b.x, b.y); o.w = h2(b.z, b.w);
    *(uint4*)(out + (size_t)i * 8) = o;
}

// ---------------------------------------------------------------------------
// GroupNorm -> transposed fp16 output xnT[b][t][c]
// ---------------------------------------------------------------------------
__global__ __launch_bounds__(256) void gn_kernel(
    const float* __restrict__ x, const float* __restrict__ sc,
    const float* __restrict__ bi, __half* __restrict__ xnT)
{
    int b = blockIdx.x >> 5;
    int g = blockIdx.x & 31;
    int c0 = g * CPG;
    const float* base = x + ((size_t)b * CC + c0) * TT;
    int tid = threadIdx.x;

    float s = 0.f, ss = 0.f;
    for (int i = tid; i < 4096; i += 256) {
        float4 v = *(const float4*)(base + (size_t)i * 4);
        s  += v.x + v.y + v.z + v.w;
        ss += v.x * v.x + v.y * v.y + v.z * v.z + v.w * v.w;
    }
    __shared__ float rs[8], rss[8];
    #pragma unroll
    for (int off = 16; off >= 1; off >>= 1) {
        s  += __shfl_xor_sync(0xffffffffu, s,  off);
        ss += __shfl_xor_sync(0xffffffffu, ss, off);
    }
    int warp = tid >> 5, lane = tid & 31;
    if (lane == 0) { rs[warp] = s; rss[warp] = ss; }
    __syncthreads();
    if (warp == 0) {
        s  = (lane < 8) ? rs[lane]  : 0.f;
        ss = (lane < 8) ? rss[lane] : 0.f;
        #pragma unroll
        for (int off = 4; off >= 1; off >>= 1) {
            s  += __shfl_xor_sync(0xffffffffu, s,  off);
            ss += __shfl_xor_sync(0xffffffffu, ss, off);
        }
        if (lane == 0) { rs[0] = s; rss[0] = ss; }
    }
    __syncthreads();
    float mu   = rs[0] * (1.f / 16384.f);
    float var  = rss[0] * (1.f / 16384.f) - mu * mu;
    float rstd = rsqrtf(var + 1e-5f);

    float a[16], bo[16];
    #pragma unroll
    for (int i = 0; i < 16; i++) {
        a[i]  = rstd * sc[c0 + i];
        bo[i] = bi[c0 + i] - mu * a[i];
    }
    for (int t = tid; t < TT; t += 256) {
        uint32_t u[8];
        #pragma unroll
        for (int i = 0; i < 8; i++) {
            float v0 = base[(size_t)(2 * i)     * TT + t] * a[2 * i]     + bo[2 * i];
            float v1 = base[(size_t)(2 * i + 1) * TT + t] * a[2 * i + 1] + bo[2 * i + 1];
            u[i] = h2(v0, v1);
        }
        __half* op = xnT + ((size_t)b * TT + t) * CC + c0;
        *(uint4*)(op)     = make_uint4(u[0], u[1], u[2], u[3]);
        *(uint4*)(op + 8) = make_uint4(u[4], u[5], u[6], u[7]);
    }
}

// ---------------------------------------------------------------------------
// FP16 GEMM, cp.async + ldmatrix: D[b][m][n] = sum_k A[m][k] B[b][n][k]
// A fp16 [M][512], B fp16 [b][1024][512]. Tile 128x128x64, 3-stage pipeline.
// 8 warps: wm = wid&1 (64 rows), wn = wid>>1 (32 cols).
// ---------------------------------------------------------------------------
template<bool HALF_OUT>
__global__ __launch_bounds__(256) void gemm_tc(
    const __half* __restrict__ A, const __half* __restrict__ B,
    const float* __restrict__ bias, const float* __restrict__ res,
    void* __restrict__ out, int M)
{
    const int K = 512, N = 1024;
    extern __shared__ char smc[];
    uint32_t sbase = smem_u32(smc);

    int tid = threadIdx.x, wid = tid >> 5, lane = tid & 31;
    int n0 = blockIdx.x * 128, m0 = blockIdx.y * 128;
    size_t bb = blockIdx.z;
    const __half* Ab = A + (size_t)m0 * K;
    const __half* Bb = B + bb * (size_t)N * K + (size_t)n0 * K;

    int wm = wid & 1, wn = wid >> 1;
    int l7 = lane & 7, quad = lane >> 3;

    // per-stage: A 128x64 halfs (16KB) + B 128x64 halfs (16KB)
    auto stage_load = [&](int buf, int k0) {
        uint32_t so = sbase + buf * 32768;
        #pragma unroll
        for (int i = 0; i < 4; i++) {
            int idx = tid + i * 256;
            int row = idx >> 3, c8 = idx & 7;
            cp16(so + swz(row * 128 + c8 * 16),
                 Ab + (size_t)row * K + k0 + c8 * 8);
        }
        #pragma unroll
        for (int i = 0; i < 4; i++) {
            int idx = tid + i * 256;
            int row = idx >> 3, c8 = idx & 7;
            cp16(so + 16384 + swz(row * 128 + c8 * 16),
                 Bb + (size_t)row * K + k0 + c8 * 8);
        }
        cp_commit();
    };

    stage_load(0, 0);
    stage_load(1, 64);
    stage_load(2, 128);

    float acc[4][4][4] = {};

    #pragma unroll 1
    for (int ks = 0; ks < 8; ks++) {
        if (ks < 6)      cp_wait<2>();
        else if (ks < 7) cp_wait<1>();
        else             cp_wait<0>();
        __syncthreads();

        uint32_t Ao = sbase + (ks % 3) * 32768;
        uint32_t Bo = Ao + 16384;
        #pragma unroll
        for (int kq = 0; kq < 4; kq++) {
            uint4 af[4], bf[2];
            #pragma unroll
            for (int i = 0; i < 4; i++) {
                int r  = wm * 64 + i * 16 + l7 + ((quad & 1) << 3);
                int kc = kq * 32 + ((quad >> 1) << 4);
                af[i] = ldsm4(Ao + swz(r * 128 + kc));
            }
            #pragma unroll
            for (int j = 0; j < 2; j++) {
                int r  = wn * 32 + j * 16 + l7 + ((quad >> 1) << 3);
                int kc = kq * 32 + ((quad & 1) << 4);
                bf[j] = ldsm4(Bo + swz(r * 128 + kc));
            }
            #pragma unroll
            for (int i = 0; i < 4; i++) {
                mma_f16(acc[i][0][0], acc[i][0][1], acc[i][0][2], acc[i][0][3],
                        af[i].x, af[i].y, af[i].z, af[i].w, bf[0].x, bf[0].y);
                mma_f16(acc[i][1][0], acc[i][1][1], acc[i][1][2], acc[i][1][3],
                        af[i].x, af[i].y, af[i].z, af[i].w, bf[0].z, bf[0].w);
                mma_f16(acc[i][2][0], acc[i][2][1], acc[i][2][2], acc[i][2][3],
                        af[i].x, af[i].y, af[i].z, af[i].w, bf[1].x, bf[1].y);
                mma_f16(acc[i][3][0], acc[i][3][1], acc[i][3][2], acc[i][3][3],
                        af[i].x, af[i].y, af[i].z, af[i].w, bf[1].z, bf[1].w);
            }
        }
        __syncthreads();
        if (ks + 3 < 8) stage_load(ks % 3, (ks + 3) * 64);
    }

    // ---- epilogue ----
    int g = lane >> 2, t = lane & 3;
    #pragma unroll
    for (int i = 0; i < 4; i++) {
        int m = m0 + wm * 64 + i * 16 + g;
        float bv0 = bias[m], bv1 = bias[m + 8];
        #pragma unroll
        for (int j = 0; j < 4; j++) {
            int n = n0 + wn * 32 + j * 8 + t * 2;
            if (HALF_OUT) {
                __half* ob = (__half*)out + ((size_t)bb * M + m) * N + n;
                *(uint32_t*)ob = h2(acc[i][j][0] + bv0, acc[i][j][1] + bv0);
                *(uint32_t*)(ob + (size_t)8 * N) =
                    h2(acc[i][j][2] + bv1, acc[i][j][3] + bv1);
            } else {
                size_t o0 = ((size_t)bb * M + m) * N + n;
                size_t o1 = o0 + (size_t)8 * N;
                float2 r0 = *(const float2*)(res + o0);
                float2 r1 = *(const float2*)(res + o1);
                r0.x += acc[i][j][0] + bv0; r0.y += acc[i][j][1] + bv0;
                r1.x += acc[i][j][2] + bv1; r1.y += acc[i][j][3] + bv1;
                *(float2*)((float*)out + o0) = r0;
                *(float2*)((float*)out + o1) = r1;
            }
        }
    }
}

// ---------------------------------------------------------------------------
// Flash attention, fp16 mma.sync. Input qkvh[b][o][t] fp16; output
// attnT[b][t][c] fp16.
// ---------------------------------------------------------------------------
__global__ __launch_bounds__(256) void attn_tc(
    const __half* __restrict__ qkv, __half* __restrict__ attnT)
{
    __shared__ uint32_t sm_u[8448];
    uint32_t* sQ = sm_u;                   // [mt8][kt4][128]
    uint32_t* sK = sm_u + 4096;            // [kt4][nt8][64]
    uint32_t* sV = sm_u + 6144;            // [kt4][nt8][64]
    __half*   sOh = (__half*)sm_u;         // [q128][stride 72]

    int t0 = blockIdx.x * 128;
    int h  = blockIdx.y;
    int b  = blockIdx.z;
    const __half* qb = qkv + ((size_t)b * M_QKV + h * HD) * TT;
    const __half* kb = qb + (size_t)CC * TT;
    const __half* vb = qb + (size_t)2 * CC * TT;

    int tid  = threadIdx.x;
    int wid  = tid >> 5;
    int lane = tid & 31;
    int group = lane >> 2, tig = lane & 3;
    const uint32_t QS = 0x30003000u;       // half2(0.125)

    #pragma unroll
    for (int i = 0; i < 4; i++) {
        int f  = tid + i * 256;
        int dp = f >> 5;
        int mq = (f & 31) << 2;
        uint2 ra  = *(const uint2*)(qb + (size_t)(2 * dp) * TT + t0 + mq);
        uint2 rb2 = *(const uint2*)(qb + (size_t)(2 * dp + 1) * TT + t0 + mq);
        uint32_t u[4];
        u[0] = hmul2u(__byte_perm(ra.x, rb2.x, 0x5410), QS);
        u[1] = hmul2u(__byte_perm(ra.x, rb2.x, 0x7632), QS);
        u[2] = hmul2u(__byte_perm(ra.y, rb2.y, 0x5410), QS);
        u[3] = hmul2u(__byte_perm(ra.y, rb2.y, 0x7632), QS);
        int t  = dp & 3;
        int kh = (dp >> 2) & 1;
        int kt = dp >> 3;
        #pragma unroll
        for (int j = 0; j < 4; j++) {
            int m = mq + j;
            int mt = m >> 4, g = m & 7;
            int r = ((m >> 3) & 1) | (kh << 1);
            sQ[((mt * 4 + kt) << 7) + ((g * 4 + t) << 2) + r] = u[j];
        }
    }
    __syncthreads();

    uint4 qa[4];
    #pragma unroll
    for (int kt = 0; kt < 4; kt++)
        qa[kt] = *(const uint4*)&sQ[((wid * 4 + kt) << 7) + (lane << 2)];

    float o[8][4] = {};
    float m0r = -1e30f, m1r = -1e30f, l0r = 0.f, l1r = 0.f;

    for (int c0 = 0; c0 < TT; c0 += 64) {
        __syncthreads();
        #pragma unroll
        for (int i = 0; i < 2; i++) {
            int f  = tid + i * 256;
            int dp = f >> 4;
            int tq = (f & 15) << 2;
            uint2 ra  = *(const uint2*)(kb + (size_t)(2 * dp) * TT + c0 + tq);
            uint2 rb2 = *(const uint2*)(kb + (size_t)(2 * dp + 1) * TT + c0 + tq);
            int t  = dp & 3;
            int r  = (dp >> 2) & 1;
            int kt = dp >> 3;
            int nt = tq >> 3;
            uint32_t* base = &sK[((kt * 8 + nt) << 6) + ((tq & 7) * 4 + t) * 2 + r];
            base[0]  = __byte_perm(ra.x, rb2.x, 0x5410);
            base[8]  = __byte_perm(ra.x, rb2.x, 0x7632);
            base[16] = __byte_perm(ra.y, rb2.y, 0x5410);
            base[24] = __byte_perm(ra.y, rb2.y, 0x7632);
        }
        #pragma unroll
        for (int i = 0; i < 4; i++) {
            int f  = tid + i * 256;
            int d  = f >> 4;
            int tq = (f & 15) << 2;
            uint2 v = *(const uint2*)(vb + (size_t)d * TT + c0 + tq);
            int kt = tq >> 4;
            int kh = (tq >> 3) & 1;
            int t0i = (tq & 7) >> 1;
            int nt = d >> 3;
            uint32_t* base = &sV[((kt * 8 + nt) << 6) + ((d & 7) * 4 + t0i) * 2 + kh];
            base[0] = v.x;
            base[2] = v.y;
        }
        __syncthreads();

        float s[8][4] = {};
        #pragma unroll
        for (int kt = 0; kt < 4; kt++) {
            #pragma unroll
            for (int nt = 0; nt < 8; nt++) {
                uint2 bf = *(const uint2*)&sK[((kt * 8 + nt) << 6) + (lane << 1)];
                mma_f16(s[nt][0], s[nt][1], s[nt][2], s[nt][3],
                        qa[kt].x, qa[kt].y, qa[kt].z, qa[kt].w, bf.x, bf.y);
            }
        }

        float mx0 = -1e30f, mx1 = -1e30f;
        #pragma unroll
        for (int nt = 0; nt < 8; nt++) {
            mx0 = fmaxf(mx0, fmaxf(s[nt][0], s[nt][1]));
            mx1 = fmaxf(mx1, fmaxf(s[nt][2], s[nt][3]));
        }
        mx0 = fmaxf(mx0, __shfl_xor_sync(0xffffffffu, mx0, 1));
        mx0 = fmaxf(mx0, __shfl_xor_sync(0xffffffffu, mx0, 2));
        mx1 = fmaxf(mx1, __shfl_xor_sync(0xffffffffu, mx1, 1));
        mx1 = fmaxf(mx1, __shfl_xor_sync(0xffffffffu, mx1, 2));
        float nm0 = fmaxf(m0r, mx0), nm1 = fmaxf(m1r, mx1);
        float cr0 = __expf(m0r - nm0), cr1 = __expf(m1r - nm1);
        m0r = nm0; m1r = nm1;
        float sum0 = 0.f, sum1 = 0.f;
        #pragma unroll
        for (int nt = 0; nt < 8; nt++) {
            s[nt][0] = __expf(s[nt][0] - nm0);
            s[nt][1] = __expf(s[nt][1] - nm0);
            s[nt][2] = __expf(s[nt][2] - nm1);
            s[nt][3] = __expf(s[nt][3] - nm1);
            sum0 += s[nt][0] + s[nt][1];
            sum1 += s[nt][2] + s[nt][3];
        }
        sum0 += __shfl_xor_sync(0xffffffffu, sum0, 1);
        sum0 += __shfl_xor_sync(0xffffffffu, sum0, 2);
        sum1 += __shfl_xor_sync(0xffffffffu, sum1, 1);
        sum1 += __shfl_xor_sync(0xffffffffu, sum1, 2);
        l0r = l0r * cr0 + sum0;
        l1r = l1r * cr1 + sum1;
        #pragma unroll
        for (int nt = 0; nt < 8; nt++) {
            o[nt][0] *= cr0; o[nt][1] *= cr0;
            o[nt][2] *= cr1; o[nt][3] *= cr1;
        }

        #pragma unroll
        for (int kt = 0; kt < 4; kt++) {
            uint32_t a0 = h2(s[2 * kt][0],     s[2 * kt][1]);
            uint32_t a1 = h2(s[2 * kt][2],     s[2 * kt][3]);
            uint32_t a2 = h2(s[2 * kt + 1][0], s[2 * kt + 1][1]);
            uint32_t a3 = h2(s[2 * kt + 1][2], s[2 * kt + 1][3]);
            #pragma unroll
            for (int nt = 0; nt < 8; nt++) {
                uint2 bf = *(const uint2*)&sV[((kt * 8 + nt) << 6) + (lane << 1)];
                mma_f16(o[nt][0], o[nt][1], o[nt][2], o[nt][3],
                        a0, a1, a2, a3, bf.x, bf.y);
            }
        }
    }

    __syncthreads();
    float inv0 = 1.f / l0r, inv1 = 1.f / l1r;
    int q0 = wid * 16 + group;
    #pragma unroll
    for (int nt = 0; nt < 8; nt++) {
        int col = nt * 8 + tig * 2;
        sOh[(q0)     * 72 + col]     = __float2half(o[nt][0] * inv0);
        sOh[(q0)     * 72 + col + 1] = __float2half(o[nt][1] * inv0);
        sOh[(q0 + 8) * 72 + col]     = __float2half(o[nt][2] * inv1);
        sOh[(q0 + 8) * 72 + col + 1] = __float2half(o[nt][3] * inv1);
    }
    __syncthreads();
    #pragma unroll
    for (int i = 0; i < 4; i++) {
        int idx = tid + i * 256;
        int q = idx >> 3, d8 = idx & 7;
        uint4 v = *(const uint4*)(sOh + q * 72 + d8 * 8);
        *(uint4*)(attnT + ((size_t)b * TT + t0 + q) * CC + h * HD + d8 * 8) = v;
    }
}

// ---------------------------------------------------------------------------
extern "C" void kernel_launch(void* const* d_in, const int* in_sizes, int n_in,
                              void* d_out, int out_size)
{
    const float* x       = (const float*)d_in[0];
    const float* gn_sc   = (const float*)d_in[1];
    const float* gn_bi   = (const float*)d_in[2];
    const float* qkv_w   = (const float*)d_in[3];
    const float* qkv_b   = (const float*)d_in[4];
    const float* proj_w  = (const float*)d_in[5];
    const float* proj_b  = (const float*)d_in[6];
    float* out = (float*)d_out;

    __half *wq, *wp, *xnT, *qkvh, *attnT;
    cudaGetSymbolAddress((void**)&wq,    g_wq);
    cudaGetSymbolAddress((void**)&wp,    g_wp);
    cudaGetSymbolAddress((void**)&xnT,   g_xnT);
    cudaGetSymbolAddress((void**)&qkvh,  g_qkvh);
    cudaGetSymbolAddress((void**)&attnT, g_attnT);

    const int GEMM_SMEM = 3 * 32768;   // 96KB
    cudaFuncSetAttribute(gemm_tc<true>,
                         cudaFuncAttributeMaxDynamicSharedMemorySize, GEMM_SMEM);
    cudaFuncSetAttribute(gemm_tc<false>,
                         cudaFuncAttributeMaxDynamicSharedMemorySize, GEMM_SMEM);

    cvt_kernel<<<(M_QKV * CC / 8 + 255) / 256, 256>>>(qkv_w, wq, M_QKV * CC / 8);
    cvt_kernel<<<(CC * CC / 8 + 255) / 256, 256>>>(proj_w, wp, CC * CC / 8);

    gn_kernel<<<BB * NG, 256>>>(x, gn_sc, gn_bi, xnT);

    // QKV GEMM: [b][o][t] fp16
    gemm_tc<true><<<dim3(8, M_QKV / 128, BB), 256, GEMM_SMEM>>>(
        wq, xnT, qkv_b, nullptr, qkvh, M_QKV);

    // Attention -> attnT[b][t][c] fp16
    attn_tc<<<dim3(TT / 128, NH, BB), 256>>>(qkvh, attnT);

    // Proj GEMM + bias + residual -> out fp32 [b][c][t]
    gemm_tc<false><<<dim3(8, CC / 128, BB), 256, GEMM_SMEM>>>(
        wp, attnT, proj_b, x, out, CC);
}

// round 6
// speedup vs baseline: 10.2191x; 1.4586x over previous
#include <cuda_runtime.h>
#include <cuda_fp16.h>
#include <math.h>
#include <stdint.h>

// Problem constants
#define BB   16
#define CC   512
#define TT   1024
#define NH   8
#define HD   64
#define NG   32
#define CPG  16
#define M_QKV 1536

// Scratch (fp16)
__device__ __half g_wq   [(size_t)M_QKV * CC];
__device__ __half g_wp   [(size_t)CC * CC];
__device__ __half g_xnT  [(size_t)BB * TT * CC];    // [b][t][c]
__device__ __half g_qkvh [(size_t)BB * M_QKV * TT]; // [b][o][t]
__device__ __half g_attnT[(size_t)BB * TT * CC];    // [b][t][c]

// ---------------------------------------------------------------------------
// helpers
// ---------------------------------------------------------------------------
__device__ __forceinline__ uint32_t h2(float lo, float hi) {
    uint32_t u;
    asm("cvt.rn.f16x2.f32 %0, %2, %1;" : "=r"(u) : "f"(lo), "f"(hi));
    return u;
}
__device__ __forceinline__ float ex2f(float x) {
    float y;
    asm("ex2.approx.ftz.f32 %0, %1;" : "=f"(y) : "f"(x));
    return y;
}
__device__ __forceinline__ uint32_t smem_u32(const void* p) {
    uint32_t a;
    asm("{ .reg .u64 t; cvta.to.shared.u64 t, %1; cvt.u32.u64 %0, t; }"
        : "=r"(a) : "l"(p));
    return a;
}
__device__ __forceinline__ void cp16(uint32_t s, const void* g) {
    asm volatile("cp.async.cg.shared.global [%0], [%1], 16;"
                 :: "r"(s), "l"(g) : "memory");
}
__device__ __forceinline__ void cp_commit() {
    asm volatile("cp.async.commit_group;" ::: "memory");
}
template<int W>
__device__ __forceinline__ void cp_wait() {
    asm volatile("cp.async.wait_group %0;" :: "n"(W) : "memory");
}
__device__ __forceinline__ uint4 ldsm4(uint32_t a) {
    uint4 r;
    asm volatile("ldmatrix.sync.aligned.m8n8.x4.shared.b16 {%0,%1,%2,%3}, [%4];"
                 : "=r"(r.x), "=r"(r.y), "=r"(r.z), "=r"(r.w) : "r"(a));
    return r;
}
__device__ __forceinline__ uint4 ldsm4t(uint32_t a) {
    uint4 r;
    asm volatile("ldmatrix.sync.aligned.m8n8.x4.trans.shared.b16 {%0,%1,%2,%3}, [%4];"
                 : "=r"(r.x), "=r"(r.y), "=r"(r.z), "=r"(r.w) : "r"(a));
    return r;
}
__device__ __forceinline__ uint32_t swz(uint32_t b) { return b ^ ((b >> 3) & 0x70); }

__device__ __forceinline__ void mma_f16(
    float& c0, float& c1, float& c2, float& c3,
    uint32_t a0, uint32_t a1, uint32_t a2, uint32_t a3,
    uint32_t b0, uint32_t b1)
{
    asm volatile(
        "mma.sync.aligned.m16n8k16.row.col.f32.f16.f16.f32 "
        "{%0,%1,%2,%3}, {%4,%5,%6,%7}, {%8,%9}, {%0,%1,%2,%3};"
        : "+f"(c0), "+f"(c1), "+f"(c2), "+f"(c3)
        : "r"(a0), "r"(a1), "r"(a2), "r"(a3), "r"(b0), "r"(b1));
}

// ---------------------------------------------------------------------------
// fp32 -> fp16 weight conversion
// ---------------------------------------------------------------------------
__global__ __launch_bounds__(256) void cvt_kernel(
    const float* __restrict__ in, __half* __restrict__ out, int n8)
{
    int i = blockIdx.x * 256 + threadIdx.x;
    if (i >= n8) return;
    float4 a = *(const float4*)(in + (size_t)i * 8);
    float4 b = *(const float4*)(in + (size_t)i * 8 + 4);
    uint4 o;
    o.x = h2(a.x, a.y); o.y = h2(a.z, a.w);
    o.z = h2(b.x, b.y); o.w = h2(b.z, b.w);
    *(uint4*)(out + (size_t)i * 8) = o;
}

// ---------------------------------------------------------------------------
// GroupNorm -> transposed fp16 output xnT[b][t][c]
// ---------------------------------------------------------------------------
__global__ __launch_bounds__(256) void gn_kernel(
    const float* __restrict__ x, const float* __restrict__ sc,
    const float* __restrict__ bi, __half* __restrict__ xnT)
{
    int b = blockIdx.x >> 5;
    int g = blockIdx.x & 31;
    int c0 = g * CPG;
    const float* base = x + ((size_t)b * CC + c0) * TT;
    int tid = threadIdx.x;

    float s = 0.f, ss = 0.f;
    for (int i = tid; i < 4096; i += 256) {
        float4 v = *(const float4*)(base + (size_t)i * 4);
        s  += v.x + v.y + v.z + v.w;
        ss += v.x * v.x + v.y * v.y + v.z * v.z + v.w * v.w;
    }
    __shared__ float rs[8], rss[8];
    #pragma unroll
    for (int off = 16; off >= 1; off >>= 1) {
        s  += __shfl_xor_sync(0xffffffffu, s,  off);
        ss += __shfl_xor_sync(0xffffffffu, ss, off);
    }
    int warp = tid >> 5, lane = tid & 31;
    if (lane == 0) { rs[warp] = s; rss[warp] = ss; }
    __syncthreads();
    if (warp == 0) {
        s  = (lane < 8) ? rs[lane]  : 0.f;
        ss = (lane < 8) ? rss[lane] : 0.f;
        #pragma unroll
        for (int off = 4; off >= 1; off >>= 1) {
            s  += __shfl_xor_sync(0xffffffffu, s,  off);
            ss += __shfl_xor_sync(0xffffffffu, ss, off);
        }
        if (lane == 0) { rs[0] = s; rss[0] = ss; }
    }
    __syncthreads();
    float mu   = rs[0] * (1.f / 16384.f);
    float var  = rss[0] * (1.f / 16384.f) - mu * mu;
    float rstd = rsqrtf(var + 1e-5f);

    float a[16], bo[16];
    #pragma unroll
    for (int i = 0; i < 16; i++) {
        a[i]  = rstd * sc[c0 + i];
        bo[i] = bi[c0 + i] - mu * a[i];
    }
    for (int t = tid; t < TT; t += 256) {
        uint32_t u[8];
        #pragma unroll
        for (int i = 0; i < 8; i++) {
            float v0 = base[(size_t)(2 * i)     * TT + t] * a[2 * i]     + bo[2 * i];
            float v1 = base[(size_t)(2 * i + 1) * TT + t] * a[2 * i + 1] + bo[2 * i + 1];
            u[i] = h2(v0, v1);
        }
        __half* op = xnT + ((size_t)b * TT + t) * CC + c0;
        *(uint4*)(op)     = make_uint4(u[0], u[1], u[2], u[3]);
        *(uint4*)(op + 8) = make_uint4(u[4], u[5], u[6], u[7]);
    }
}

// ---------------------------------------------------------------------------
// FP16 GEMM, cp.async + ldmatrix: D[b][m][n] = sum_k A[m][k] B[b][n][k]
// ---------------------------------------------------------------------------
template<bool HALF_OUT>
__global__ __launch_bounds__(256) void gemm_tc(
    const __half* __restrict__ A, const __half* __restrict__ B,
    const float* __restrict__ bias, const float* __restrict__ res,
    void* __restrict__ out, int M)
{
    const int K = 512, N = 1024;
    extern __shared__ char smc[];
    uint32_t sbase = smem_u32(smc);

    int tid = threadIdx.x, wid = tid >> 5, lane = tid & 31;
    int n0 = blockIdx.x * 128, m0 = blockIdx.y * 128;
    size_t bb = blockIdx.z;
    const __half* Ab = A + (size_t)m0 * K;
    const __half* Bb = B + bb * (size_t)N * K + (size_t)n0 * K;

    int wm = wid & 1, wn = wid >> 1;
    int l7 = lane & 7, quad = lane >> 3;

    auto stage_load = [&](int buf, int k0) {
        uint32_t so = sbase + buf * 32768;
        #pragma unroll
        for (int i = 0; i < 4; i++) {
            int idx = tid + i * 256;
            int row = idx >> 3, c8 = idx & 7;
            cp16(so + swz(row * 128 + c8 * 16),
                 Ab + (size_t)row * K + k0 + c8 * 8);
        }
        #pragma unroll
        for (int i = 0; i < 4; i++) {
            int idx = tid + i * 256;
            int row = idx >> 3, c8 = idx & 7;
            cp16(so + 16384 + swz(row * 128 + c8 * 16),
                 Bb + (size_t)row * K + k0 + c8 * 8);
        }
        cp_commit();
    };

    stage_load(0, 0);
    stage_load(1, 64);
    stage_load(2, 128);

    float acc[4][4][4] = {};

    #pragma unroll 1
    for (int ks = 0; ks < 8; ks++) {
        if (ks < 6)      cp_wait<2>();
        else if (ks < 7) cp_wait<1>();
        else             cp_wait<0>();
        __syncthreads();

        uint32_t Ao = sbase + (ks % 3) * 32768;
        uint32_t Bo = Ao + 16384;
        #pragma unroll
        for (int kq = 0; kq < 4; kq++) {
            uint4 af[4], bf[2];
            #pragma unroll
            for (int i = 0; i < 4; i++) {
                int r  = wm * 64 + i * 16 + l7 + ((quad & 1) << 3);
                int kc = kq * 32 + ((quad >> 1) << 4);
                af[i] = ldsm4(Ao + swz(r * 128 + kc));
            }
            #pragma unroll
            for (int j = 0; j < 2; j++) {
                int r  = wn * 32 + j * 16 + l7 + ((quad >> 1) << 3);
                int kc = kq * 32 + ((quad & 1) << 4);
                bf[j] = ldsm4(Bo + swz(r * 128 + kc));
            }
            #pragma unroll
            for (int i = 0; i < 4; i++) {
                mma_f16(acc[i][0][0], acc[i][0][1], acc[i][0][2], acc[i][0][3],
                        af[i].x, af[i].y, af[i].z, af[i].w, bf[0].x, bf[0].y);
                mma_f16(acc[i][1][0], acc[i][1][1], acc[i][1][2], acc[i][1][3],
                        af[i].x, af[i].y, af[i].z, af[i].w, bf[0].z, bf[0].w);
                mma_f16(acc[i][2][0], acc[i][2][1], acc[i][2][2], acc[i][2][3],
                        af[i].x, af[i].y, af[i].z, af[i].w, bf[1].x, bf[1].y);
                mma_f16(acc[i][3][0], acc[i][3][1], acc[i][3][2], acc[i][3][3],
                        af[i].x, af[i].y, af[i].z, af[i].w, bf[1].z, bf[1].w);
            }
        }
        __syncthreads();
        if (ks + 3 < 8) stage_load(ks % 3, (ks + 3) * 64);
    }

    int g = lane >> 2, t = lane & 3;
    #pragma unroll
    for (int i = 0; i < 4; i++) {
        int m = m0 + wm * 64 + i * 16 + g;
        float bv0 = bias[m], bv1 = bias[m + 8];
        #pragma unroll
        for (int j = 0; j < 4; j++) {
            int n = n0 + wn * 32 + j * 8 + t * 2;
            if (HALF_OUT) {
                __half* ob = (__half*)out + ((size_t)bb * M + m) * N + n;
                *(uint32_t*)ob = h2(acc[i][j][0] + bv0, acc[i][j][1] + bv0);
                *(uint32_t*)(ob + (size_t)8 * N) =
                    h2(acc[i][j][2] + bv1, acc[i][j][3] + bv1);
            } else {
                size_t o0 = ((size_t)bb * M + m) * N + n;
                size_t o1 = o0 + (size_t)8 * N;
                float2 r0 = *(const float2*)(res + o0);
                float2 r1 = *(const float2*)(res + o1);
                r0.x += acc[i][j][0] + bv0; r0.y += acc[i][j][1] + bv0;
                r1.x += acc[i][j][2] + bv1; r1.y += acc[i][j][3] + bv1;
                *(float2*)((float*)out + o0) = r0;
                *(float2*)((float*)out + o1) = r1;
            }
        }
    }
}

// ---------------------------------------------------------------------------
// Flash attention v2: cp.async + ldmatrix. Block = 128 queries, 8 warps.
// qkv fp16 [b][o][t] (o = s*512 + h*64 + d).
// Q/K tiles [d][t] -> ldmatrix.x4.trans; V [d][s] -> ldmatrix.x4.
// smem: Q 16KB @0, 3 K/V stages (K 8KB + V 8KB) @16KB. Scale folded in exp2.
// ---------------------------------------------------------------------------
__global__ __launch_bounds__(256) void attn_tc(
    const __half* __restrict__ qkv, __half* __restrict__ attnT)
{
    extern __shared__ char smc[];
    uint32_t sb = smem_u32(smc);

    int t0 = blockIdx.x * 128;
    int h  = blockIdx.y;
    int b  = blockIdx.z;
    const __half* qb = qkv + ((size_t)b * M_QKV + h * HD) * TT;
    const __half* kb = qb + (size_t)CC * TT;
    const __half* vb = qb + (size_t)2 * CC * TT;

    int tid  = threadIdx.x;
    int wid  = tid >> 5;
    int lane = tid & 31;
    int group = lane >> 2, tig = lane & 3;
    const float SC = 0.125f * 1.44269504f;   // scale * log2(e)

    // ---- Q tile: 64 d-rows x 128 tq (256B rows, swizzled per 128B half) ----
    #pragma unroll
    for (int i = 0; i < 4; i++) {
        int idx = tid + i * 256;          // 1024 cp16
        int d = idx >> 4, c16 = idx & 15;
        uint32_t c = c16 * 16;
        uint32_t addr = d * 256 + (c & 128) + ((c & 127) ^ ((uint32_t)(d & 7) << 4));
        cp16(sb + addr, qb + (size_t)d * TT + t0 + c16 * 8);
    }
    cp_commit();

    auto stage_load = [&](int buf, int c0) {
        uint32_t so = sb + 16384 + buf * 16384;
        #pragma unroll
        for (int i = 0; i < 2; i++) {
            int idx = tid + i * 256;      // 512 cp16
            int d = idx >> 3, c8 = idx & 7;
            uint32_t cl = (uint32_t)(c8 * 16) ^ ((uint32_t)(d & 7) << 4);
            cp16(so + d * 128 + cl, kb + (size_t)d * TT + c0 + c8 * 8);
        }
        #pragma unroll
        for (int i = 0; i < 2; i++) {
            int idx = tid + i * 256;
            int d = idx >> 3, c8 = idx & 7;
            uint32_t cl = (uint32_t)(c8 * 16) ^ ((uint32_t)(d & 7) << 4);
            cp16(so + 8192 + d * 128 + cl, vb + (size_t)d * TT + c0 + c8 * 8);
        }
        cp_commit();
    };

    stage_load(0, 0);
    stage_load(1, 64);
    stage_load(2, 128);
    cp_wait<2>();                   // Q + stage0 complete
    __syncthreads();

    // ---- per-warp Q fragments (m16 = wid*16) via ldmatrix.trans ----
    int m0w = wid * 16;
    uint32_t qhalf = (m0w & 64) ? 128u : 0u;
    uint4 qa[4];
    #pragma unroll
    for (int kt = 0; kt < 4; kt++) {
        int dq = kt * 16 + ((lane >> 4) & 1) * 8 + (lane & 7);
        int mq = m0w + ((lane >> 3) & 1) * 8;
        uint32_t addr = sb + dq * 256 + qhalf +
            (((uint32_t)((mq & 63) * 2)) ^ ((uint32_t)(dq & 7) << 4));
        qa[kt] = ldsm4t(addr);
    }

    float o[8][4] = {};
    float m0r = -1e30f, m1r = -1e30f, l0r = 0.f, l1r = 0.f;

    #pragma unroll 1
    for (int ks = 0; ks < 16; ks++) {
        uint32_t so = sb + 16384 + (ks % 3) * 16384;

        // ---- S = Q K^T ----
        float s[8][4] = {};
        #pragma unroll
        for (int kt = 0; kt < 4; kt++) {
            #pragma unroll
            for (int np = 0; np < 4; np++) {
                int dk  = kt * 16 + ((lane >> 3) & 1) * 8 + (lane & 7);
                int key = np * 16 + ((lane >> 4) & 1) * 8;
                uint4 kf = ldsm4t(so + dk * 128 +
                    (((uint32_t)(key * 2)) ^ ((uint32_t)(dk & 7) << 4)));
                mma_f16(s[2*np][0], s[2*np][1], s[2*np][2], s[2*np][3],
                        qa[kt].x, qa[kt].y, qa[kt].z, qa[kt].w, kf.x, kf.y);
                mma_f16(s[2*np+1][0], s[2*np+1][1], s[2*np+1][2], s[2*np+1][3],
                        qa[kt].x, qa[kt].y, qa[kt].z, qa[kt].w, kf.z, kf.w);
            }
        }

        // ---- online softmax (scale folded into exp2) ----
        float mx0 = -1e30f, mx1 = -1e30f;
        #pragma unroll
        for (int nt = 0; nt < 8; nt++) {
            mx0 = fmaxf(mx0, fmaxf(s[nt][0], s[nt][1]));
            mx1 = fmaxf(mx1, fmaxf(s[nt][2], s[nt][3]));
        }
        mx0 = fmaxf(mx0, __shfl_xor_sync(0xffffffffu, mx0, 1));
        mx0 = fmaxf(mx0, __shfl_xor_sync(0xffffffffu, mx0, 2));
        mx1 = fmaxf(mx1, __shfl_xor_sync(0xffffffffu, mx1, 1));
        mx1 = fmaxf(mx1, __shfl_xor_sync(0xffffffffu, mx1, 2));
        float nm0 = fmaxf(m0r, mx0), nm1 = fmaxf(m1r, mx1);
        float cr0 = ex2f((m0r - nm0) * SC), cr1 = ex2f((m1r - nm1) * SC);
        m0r = nm0; m1r = nm1;
        float b0c = nm0 * SC, b1c = nm1 * SC;
        float sum0 = 0.f, sum1 = 0.f;
        #pragma unroll
        for (int nt = 0; nt < 8; nt++) {
            s[nt][0] = ex2f(fmaf(s[nt][0], SC, -b0c));
            s[nt][1] = ex2f(fmaf(s[nt][1], SC, -b0c));
            s[nt][2] = ex2f(fmaf(s[nt][2], SC, -b1c));
            s[nt][3] = ex2f(fmaf(s[nt][3], SC, -b1c));
            sum0 += s[nt][0] + s[nt][1];
            sum1 += s[nt][2] + s[nt][3];
        }
        sum0 += __shfl_xor_sync(0xffffffffu, sum0, 1);
        sum0 += __shfl_xor_sync(0xffffffffu, sum0, 2);
        sum1 += __shfl_xor_sync(0xffffffffu, sum1, 1);
        sum1 += __shfl_xor_sync(0xffffffffu, sum1, 2);
        l0r = l0r * cr0 + sum0;
        l1r = l1r * cr1 + sum1;
        #pragma unroll
        for (int nt = 0; nt < 8; nt++) {
            o[nt][0] *= cr0; o[nt][1] *= cr0;
            o[nt][2] *= cr1; o[nt][3] *= cr1;
        }

        // ---- O += P V ----
        #pragma unroll
        for (int kt = 0; kt < 4; kt++) {
            uint32_t a0 = h2(s[2*kt][0],   s[2*kt][1]);
            uint32_t a1 = h2(s[2*kt][2],   s[2*kt][3]);
            uint32_t a2 = h2(s[2*kt+1][0], s[2*kt+1][1]);
            uint32_t a3 = h2(s[2*kt+1][2], s[2*kt+1][3]);
            #pragma unroll
            for (int np = 0; np < 4; np++) {
                int dv   = np * 16 + ((lane >> 4) & 1) * 8 + (lane & 7);
                int scol = kt * 16 + ((lane >> 3) & 1) * 8;
                uint4 vf = ldsm4(so + 8192 + dv * 128 +
                    (((uint32_t)(scol * 2)) ^ ((uint32_t)(dv & 7) << 4)));
                mma_f16(o[2*np][0], o[2*np][1], o[2*np][2], o[2*np][3],
                        a0, a1, a2, a3, vf.x, vf.y);
                mma_f16(o[2*np+1][0], o[2*np+1][1], o[2*np+1][2], o[2*np+1][3],
                        a0, a1, a2, a3, vf.z, vf.w);
            }
        }

        if (ks < 15) {
            __syncthreads();                       // done reading buffer ks%3
            if (ks + 3 < 16) stage_load(ks % 3, (ks + 3) * 64);
            if (ks <= 12)      cp_wait<2>();
            else if (ks == 13) cp_wait<1>();
            else               cp_wait<0>();
            __syncthreads();                       // stage ks+1 ready
        }
    }

    // ---- finalize: stage [q][d] fp16 in smem, write attnT[b][t][c] ----
    __syncthreads();
    __half* sOh = (__half*)(smc + 16384);          // [q128][stride 72]
    float inv0 = 1.f / l0r, inv1 = 1.f / l1r;
    int q0 = wid * 16 + group;
    #pragma unroll
    for (int nt = 0; nt < 8; nt++) {
        int col = nt * 8 + tig * 2;
        sOh[(q0)     * 72 + col]     = __float2half(o[nt][0] * inv0);
        sOh[(q0)     * 72 + col + 1] = __float2half(o[nt][1] * inv0);
        sOh[(q0 + 8) * 72 + col]     = __float2half(o[nt][2] * inv1);
        sOh[(q0 + 8) * 72 + col + 1] = __float2half(o[nt][3] * inv1);
    }
    __syncthreads();
    #pragma unroll
    for (int i = 0; i < 4; i++) {
        int idx = tid + i * 256;
        int q = idx >> 3, d8 = idx & 7;
        uint4 v = *(const uint4*)(sOh + q * 72 + d8 * 8);
        *(uint4*)(attnT + ((size_t)b * TT + t0 + q) * CC + h * HD + d8 * 8) = v;
    }
}

// ---------------------------------------------------------------------------
extern "C" void kernel_launch(void* const* d_in, const int* in_sizes, int n_in,
                              void* d_out, int out_size)
{
    const float* x       = (const float*)d_in[0];
    const float* gn_sc   = (const float*)d_in[1];
    const float* gn_bi   = (const float*)d_in[2];
    const float* qkv_w   = (const float*)d_in[3];
    const float* qkv_b   = (const float*)d_in[4];
    const float* proj_w  = (const float*)d_in[5];
    const float* proj_b  = (const float*)d_in[6];
    float* out = (float*)d_out;

    __half *wq, *wp, *xnT, *qkvh, *attnT;
    cudaGetSymbolAddress((void**)&wq,    g_wq);
    cudaGetSymbolAddress((void**)&wp,    g_wp);
    cudaGetSymbolAddress((void**)&xnT,   g_xnT);
    cudaGetSymbolAddress((void**)&qkvh,  g_qkvh);
    cudaGetSymbolAddress((void**)&attnT, g_attnT);

    const int GEMM_SMEM = 3 * 32768;   // 96KB
    const int ATTN_SMEM = 16384 + 3 * 16384;  // 64KB
    cudaFuncSetAttribute(gemm_tc<true>,
                         cudaFuncAttributeMaxDynamicSharedMemorySize, GEMM_SMEM);
    cudaFuncSetAttribute(gemm_tc<false>,
                         cudaFuncAttributeMaxDynamicSharedMemorySize, GEMM_SMEM);
    cudaFuncSetAttribute(attn_tc,
                         cudaFuncAttributeMaxDynamicSharedMemorySize, ATTN_SMEM);

    cvt_kernel<<<(M_QKV * CC / 8 + 255) / 256, 256>>>(qkv_w, wq, M_QKV * CC / 8);
    cvt_kernel<<<(CC * CC / 8 + 255) / 256, 256>>>(proj_w, wp, CC * CC / 8);

    gn_kernel<<<BB * NG, 256>>>(x, gn_sc, gn_bi, xnT);

    gemm_tc<true><<<dim3(8, M_QKV / 128, BB), 256, GEMM_SMEM>>>(
        wq, xnT, qkv_b, nullptr, qkvh, M_QKV);

    attn_tc<<<dim3(TT / 128, NH, BB), 256, ATTN_SMEM>>>(qkvh, attnT);

    gemm_tc<false><<<dim3(8, CC / 128, BB), 256, GEMM_SMEM>>>(
        wp, attnT, proj_b, x, out, CC);
}

// round 7
// speedup vs baseline: 10.3053x; 1.0084x over previous
#include <cuda_runtime.h>
#include <cuda_fp16.h>
#include <math.h>
#include <stdint.h>

// Problem constants
#define BB   16
#define CC   512
#define TT   1024
#define NH   8
#define HD   64
#define NG   32
#define CPG  16
#define M_QKV 1536

// Scratch (fp16)
__device__ __half g_wq   [(size_t)M_QKV * CC];
__device__ __half g_wp   [(size_t)CC * CC];
__device__ __half g_xnT  [(size_t)BB * TT * CC];    // [b][t][c]
__device__ __half g_qkvh [(size_t)BB * M_QKV * TT]; // [b][o][t]
__device__ __half g_attnT[(size_t)BB * TT * CC];    // [b][t][c]

// ---------------------------------------------------------------------------
// helpers
// ---------------------------------------------------------------------------
__device__ __forceinline__ uint32_t h2(float lo, float hi) {
    uint32_t u;
    asm("cvt.rn.f16x2.f32 %0, %2, %1;" : "=r"(u) : "f"(lo), "f"(hi));
    return u;
}
__device__ __forceinline__ float ex2f(float x) {
    float y;
    asm("ex2.approx.ftz.f32 %0, %1;" : "=f"(y) : "f"(x));
    return y;
}
__device__ __forceinline__ uint32_t smem_u32(const void* p) {
    uint32_t a;
    asm("{ .reg .u64 t; cvta.to.shared.u64 t, %1; cvt.u32.u64 %0, t; }"
        : "=r"(a) : "l"(p));
    return a;
}
__device__ __forceinline__ void cp16(uint32_t s, const void* g) {
    asm volatile("cp.async.cg.shared.global [%0], [%1], 16;"
                 :: "r"(s), "l"(g) : "memory");
}
__device__ __forceinline__ void cp_commit() {
    asm volatile("cp.async.commit_group;" ::: "memory");
}
template<int W>
__device__ __forceinline__ void cp_wait() {
    asm volatile("cp.async.wait_group %0;" :: "n"(W) : "memory");
}
__device__ __forceinline__ uint4 ldsm4(uint32_t a) {
    uint4 r;
    asm volatile("ldmatrix.sync.aligned.m8n8.x4.shared.b16 {%0,%1,%2,%3}, [%4];"
                 : "=r"(r.x), "=r"(r.y), "=r"(r.z), "=r"(r.w) : "r"(a));
    return r;
}
__device__ __forceinline__ uint4 ldsm4t(uint32_t a) {
    uint4 r;
    asm volatile("ldmatrix.sync.aligned.m8n8.x4.trans.shared.b16 {%0,%1,%2,%3}, [%4];"
                 : "=r"(r.x), "=r"(r.y), "=r"(r.z), "=r"(r.w) : "r"(a));
    return r;
}
__device__ __forceinline__ uint32_t swz(uint32_t b) { return b ^ ((b >> 3) & 0x70); }

__device__ __forceinline__ void mma_f16(
    float& c0, float& c1, float& c2, float& c3,
    uint32_t a0, uint32_t a1, uint32_t a2, uint32_t a3,
    uint32_t b0, uint32_t b1)
{
    asm volatile(
        "mma.sync.aligned.m16n8k16.row.col.f32.f16.f16.f32 "
        "{%0,%1,%2,%3}, {%4,%5,%6,%7}, {%8,%9}, {%0,%1,%2,%3};"
        : "+f"(c0), "+f"(c1), "+f"(c2), "+f"(c3)
        : "r"(a0), "r"(a1), "r"(a2), "r"(a3), "r"(b0), "r"(b1));
}

// ---------------------------------------------------------------------------
// fp32 -> fp16 weight conversion
// ---------------------------------------------------------------------------
__global__ __launch_bounds__(256) void cvt_kernel(
    const float* __restrict__ in, __half* __restrict__ out, int n8)
{
    int i = blockIdx.x * 256 + threadIdx.x;
    if (i >= n8) return;
    float4 a = *(const float4*)(in + (size_t)i * 8);
    float4 b = *(const float4*)(in + (size_t)i * 8 + 4);
    uint4 o;
    o.x = h2(a.x, a.y); o.y = h2(a.z, a.w);
    o.z = h2(b.x, b.y); o.w = h2(b.z, b.w);
    *(uint4*)(out + (size_t)i * 8) = o;
}

// ---------------------------------------------------------------------------
// GroupNorm, single-pass register-cached -> transposed fp16 xnT[b][t][c].
// Thread tid holds channel k (k=0..15) at t in [4*tid, 4*tid+3]:
// a 16c x 4t register tile, transposed on write (4 x 32B stores).
// ---------------------------------------------------------------------------
__global__ __launch_bounds__(256) void gn_kernel(
    const float* __restrict__ x, const float* __restrict__ sc,
    const float* __restrict__ bi, __half* __restrict__ xnT)
{
    int b = blockIdx.x >> 5;
    int g = blockIdx.x & 31;
    int c0 = g * CPG;
    const float* base = x + ((size_t)b * CC + c0) * TT;
    int tid = threadIdx.x;

    float4 v[16];
    float s = 0.f, ss = 0.f;
    #pragma unroll
    for (int k = 0; k < 16; k++) {
        v[k] = *(const float4*)(base + ((size_t)tid + k * 256) * 4);
        s  += v[k].x + v[k].y + v[k].z + v[k].w;
        ss += v[k].x * v[k].x + v[k].y * v[k].y +
              v[k].z * v[k].z + v[k].w * v[k].w;
    }
    __shared__ float rs[8], rss[8];
    #pragma unroll
    for (int off = 16; off >= 1; off >>= 1) {
        s  += __shfl_xor_sync(0xffffffffu, s,  off);
        ss += __shfl_xor_sync(0xffffffffu, ss, off);
    }
    int warp = tid >> 5, lane = tid & 31;
    if (lane == 0) { rs[warp] = s; rss[warp] = ss; }
    __syncthreads();
    if (warp == 0) {
        s  = (lane < 8) ? rs[lane]  : 0.f;
        ss = (lane < 8) ? rss[lane] : 0.f;
        #pragma unroll
        for (int off = 4; off >= 1; off >>= 1) {
            s  += __shfl_xor_sync(0xffffffffu, s,  off);
            ss += __shfl_xor_sync(0xffffffffu, ss, off);
        }
        if (lane == 0) { rs[0] = s; rss[0] = ss; }
    }
    __syncthreads();
    float mu   = rs[0] * (1.f / 16384.f);
    float var  = rss[0] * (1.f / 16384.f) - mu * mu;
    float rstd = rsqrtf(var + 1e-5f);

    float a[16], bo[16];
    #pragma unroll
    for (int k = 0; k < 16; k++) {
        a[k]  = rstd * sc[c0 + k];
        bo[k] = bi[c0 + k] - mu * a[k];
    }

    // transpose in registers: for each j (t = 4*tid + j), emit 16 channels
    #pragma unroll
    for (int j = 0; j < 4; j++) {
        uint32_t u[8];
        #pragma unroll
        for (int k = 0; k < 8; k++) {
            const float* p0 = (const float*)&v[2 * k];
            const float* p1 = (const float*)&v[2 * k + 1];
            u[k] = h2(p0[j] * a[2 * k] + bo[2 * k],
                      p1[j] * a[2 * k + 1] + bo[2 * k + 1]);
        }
        __half* op = xnT + ((size_t)b * TT + 4 * tid + j) * CC + c0;
        *(uint4*)(op)     = make_uint4(u[0], u[1], u[2], u[3]);
        *(uint4*)(op + 8) = make_uint4(u[4], u[5], u[6], u[7]);
    }
}

// ---------------------------------------------------------------------------
// FP16 GEMM, cp.async + ldmatrix (unchanged from round 6)
// ---------------------------------------------------------------------------
template<bool HALF_OUT>
__global__ __launch_bounds__(256) void gemm_tc(
    const __half* __restrict__ A, const __half* __restrict__ B,
    const float* __restrict__ bias, const float* __restrict__ res,
    void* __restrict__ out, int M)
{
    const int K = 512, N = 1024;
    extern __shared__ char smc[];
    uint32_t sbase = smem_u32(smc);

    int tid = threadIdx.x, wid = tid >> 5, lane = tid & 31;
    int n0 = blockIdx.x * 128, m0 = blockIdx.y * 128;
    size_t bb = blockIdx.z;
    const __half* Ab = A + (size_t)m0 * K;
    const __half* Bb = B + bb * (size_t)N * K + (size_t)n0 * K;

    int wm = wid & 1, wn = wid >> 1;
    int l7 = lane & 7, quad = lane >> 3;

    auto stage_load = [&](int buf, int k0) {
        uint32_t so = sbase + buf * 32768;
        #pragma unroll
        for (int i = 0; i < 4; i++) {
            int idx = tid + i * 256;
            int row = idx >> 3, c8 = idx & 7;
            cp16(so + swz(row * 128 + c8 * 16),
                 Ab + (size_t)row * K + k0 + c8 * 8);
        }
        #pragma unroll
        for (int i = 0; i < 4; i++) {
            int idx = tid + i * 256;
            int row = idx >> 3, c8 = idx & 7;
            cp16(so + 16384 + swz(row * 128 + c8 * 16),
                 Bb + (size_t)row * K + k0 + c8 * 8);
        }
        cp_commit();
    };

    stage_load(0, 0);
    stage_load(1, 64);
    stage_load(2, 128);

    float acc[4][4][4] = {};

    #pragma unroll 1
    for (int ks = 0; ks < 8; ks++) {
        if (ks < 6)      cp_wait<2>();
        else if (ks < 7) cp_wait<1>();
        else             cp_wait<0>();
        __syncthreads();

        uint32_t Ao = sbase + (ks % 3) * 32768;
        uint32_t Bo = Ao + 16384;
        #pragma unroll
        for (int kq = 0; kq < 4; kq++) {
            uint4 af[4], bf[2];
            #pragma unroll
            for (int i = 0; i < 4; i++) {
                int r  = wm * 64 + i * 16 + l7 + ((quad & 1) << 3);
                int kc = kq * 32 + ((quad >> 1) << 4);
                af[i] = ldsm4(Ao + swz(r * 128 + kc));
            }
            #pragma unroll
            for (int j = 0; j < 2; j++) {
                int r  = wn * 32 + j * 16 + l7 + ((quad >> 1) << 3);
                int kc = kq * 32 + ((quad & 1) << 4);
                bf[j] = ldsm4(Bo + swz(r * 128 + kc));
            }
            #pragma unroll
            for (int i = 0; i < 4; i++) {
                mma_f16(acc[i][0][0], acc[i][0][1], acc[i][0][2], acc[i][0][3],
                        af[i].x, af[i].y, af[i].z, af[i].w, bf[0].x, bf[0].y);
                mma_f16(acc[i][1][0], acc[i][1][1], acc[i][1][2], acc[i][1][3],
                        af[i].x, af[i].y, af[i].z, af[i].w, bf[0].z, bf[0].w);
                mma_f16(acc[i][2][0], acc[i][2][1], acc[i][2][2], acc[i][2][3],
                        af[i].x, af[i].y, af[i].z, af[i].w, bf[1].x, bf[1].y);
                mma_f16(acc[i][3][0], acc[i][3][1], acc[i][3][2], acc[i][3][3],
                        af[i].x, af[i].y, af[i].z, af[i].w, bf[1].z, bf[1].w);
            }
        }
        __syncthreads();
        if (ks + 3 < 8) stage_load(ks % 3, (ks + 3) * 64);
    }

    int g = lane >> 2, t = lane & 3;
    #pragma unroll
    for (int i = 0; i < 4; i++) {
        int m = m0 + wm * 64 + i * 16 + g;
        float bv0 = bias[m], bv1 = bias[m + 8];
        #pragma unroll
        for (int j = 0; j < 4; j++) {
            int n = n0 + wn * 32 + j * 8 + t * 2;
            if (HALF_OUT) {
                __half* ob = (__half*)out + ((size_t)bb * M + m) * N + n;
                *(uint32_t*)ob = h2(acc[i][j][0] + bv0, acc[i][j][1] + bv0);
                *(uint32_t*)(ob + (size_t)8 * N) =
                    h2(acc[i][j][2] + bv1, acc[i][j][3] + bv1);
            } else {
                size_t o0 = ((size_t)bb * M + m) * N + n;
                size_t o1 = o0 + (size_t)8 * N;
                float2 r0 = *(const float2*)(res + o0);
                float2 r1 = *(const float2*)(res + o1);
                r0.x += acc[i][j][0] + bv0; r0.y += acc[i][j][1] + bv0;
                r1.x += acc[i][j][2] + bv1; r1.y += acc[i][j][3] + bv1;
                *(float2*)((float*)out + o0) = r0;
                *(float2*)((float*)out + o1) = r1;
            }
        }
    }
}

// ---------------------------------------------------------------------------
// Flash attention v3: 4-stage cp.async pipeline, ONE __syncthreads per chunk,
// conditional O-rescale. Block = 128 queries, 8 warps.
// smem: Q 16KB @0, 4 K/V stages (K 8KB + V 8KB) @16KB = 80KB total.
// ---------------------------------------------------------------------------
__global__ __launch_bounds__(256) void attn_tc(
    const __half* __restrict__ qkv, __half* __restrict__ attnT)
{
    extern __shared__ char smc[];
    uint32_t sb = smem_u32(smc);

    int t0 = blockIdx.x * 128;
    int h  = blockIdx.y;
    int b  = blockIdx.z;
    const __half* qb = qkv + ((size_t)b * M_QKV + h * HD) * TT;
    const __half* kb = qb + (size_t)CC * TT;
    const __half* vb = qb + (size_t)2 * CC * TT;

    int tid  = threadIdx.x;
    int wid  = tid >> 5;
    int lane = tid & 31;
    int group = lane >> 2, tig = lane & 3;
    const float SC = 0.125f * 1.44269504f;   // scale * log2(e)

    // ---- Q tile: 64 d-rows x 128 tq ----
    #pragma unroll
    for (int i = 0; i < 4; i++) {
        int idx = tid + i * 256;
        int d = idx >> 4, c16 = idx & 15;
        uint32_t c = c16 * 16;
        uint32_t addr = d * 256 + (c & 128) + ((c & 127) ^ ((uint32_t)(d & 7) << 4));
        cp16(sb + addr, qb + (size_t)d * TT + t0 + c16 * 8);
    }
    cp_commit();

    auto stage_load = [&](int buf, int c0) {
        uint32_t so = sb + 16384 + buf * 16384;
        #pragma unroll
        for (int i = 0; i < 2; i++) {
            int idx = tid + i * 256;
            int d = idx >> 3, c8 = idx & 7;
            uint32_t cl = (uint32_t)(c8 * 16) ^ ((uint32_t)(d & 7) << 4);
            cp16(so + d * 128 + cl, kb + (size_t)d * TT + c0 + c8 * 8);
        }
        #pragma unroll
        for (int i = 0; i < 2; i++) {
            int idx = tid + i * 256;
            int d = idx >> 3, c8 = idx & 7;
            uint32_t cl = (uint32_t)(c8 * 16) ^ ((uint32_t)(d & 7) << 4);
            cp16(so + 8192 + d * 128 + cl, vb + (size_t)d * TT + c0 + c8 * 8);
        }
        cp_commit();
    };

    stage_load(0, 0);
    stage_load(1, 64);
    stage_load(2, 128);
    cp_wait<2>();                   // Q + stage0 complete
    __syncthreads();

    // ---- per-warp Q fragments (m16 = wid*16) via ldmatrix.trans ----
    int m0w = wid * 16;
    uint32_t qhalf = (m0w & 64) ? 128u : 0u;
    uint4 qa[4];
    #pragma unroll
    for (int kt = 0; kt < 4; kt++) {
        int dq = kt * 16 + ((lane >> 4) & 1) * 8 + (lane & 7);
        int mq = m0w + ((lane >> 3) & 1) * 8;
        uint32_t addr = sb + dq * 256 + qhalf +
            (((uint32_t)((mq & 63) * 2)) ^ ((uint32_t)(dq & 7) << 4));
        qa[kt] = ldsm4t(addr);
    }

    float o[8][4] = {};
    float m0r = -1e30f, m1r = -1e30f, l0r = 0.f, l1r = 0.f;

    #pragma unroll 1
    for (int ks = 0; ks < 16; ks++) {
        uint32_t so = sb + 16384 + (ks & 3) * 16384;

        // ---- S = Q K^T ----
        float s[8][4] = {};
        #pragma unroll
        for (int kt = 0; kt < 4; kt++) {
            #pragma unroll
            for (int np = 0; np < 4; np++) {
                int dk  = kt * 16 + ((lane >> 3) & 1) * 8 + (lane & 7);
                int key = np * 16 + ((lane >> 4) & 1) * 8;
                uint4 kf = ldsm4t(so + dk * 128 +
                    (((uint32_t)(key * 2)) ^ ((uint32_t)(dk & 7) << 4)));
                mma_f16(s[2*np][0], s[2*np][1], s[2*np][2], s[2*np][3],
                        qa[kt].x, qa[kt].y, qa[kt].z, qa[kt].w, kf.x, kf.y);
                mma_f16(s[2*np+1][0], s[2*np+1][1], s[2*np+1][2], s[2*np+1][3],
                        qa[kt].x, qa[kt].y, qa[kt].z, qa[kt].w, kf.z, kf.w);
            }
        }

        // ---- online softmax (scale folded into exp2) ----
        float mx0 = -1e30f, mx1 = -1e30f;
        #pragma unroll
        for (int nt = 0; nt < 8; nt++) {
            mx0 = fmaxf(mx0, fmaxf(s[nt][0], s[nt][1]));
            mx1 = fmaxf(mx1, fmaxf(s[nt][2], s[nt][3]));
        }
        mx0 = fmaxf(mx0, __shfl_xor_sync(0xffffffffu, mx0, 1));
        mx0 = fmaxf(mx0, __shfl_xor_sync(0xffffffffu, mx0, 2));
        mx1 = fmaxf(mx1, __shfl_xor_sync(0xffffffffu, mx1, 1));
        mx1 = fmaxf(mx1, __shfl_xor_sync(0xffffffffu, mx1, 2));
        float nm0 = fmaxf(m0r, mx0), nm1 = fmaxf(m1r, mx1);
        bool chg = (nm0 != m0r) || (nm1 != m1r);
        float om0 = m0r, om1 = m1r;
        m0r = nm0; m1r = nm1;
        float b0c = nm0 * SC, b1c = nm1 * SC;
        float sum0 = 0.f, sum1 = 0.f;
        #pragma unroll
        for (int nt = 0; nt < 8; nt++) {
            s[nt][0] = ex2f(fmaf(s[nt][0], SC, -b0c));
            s[nt][1] = ex2f(fmaf(s[nt][1], SC, -b0c));
            s[nt][2] = ex2f(fmaf(s[nt][2], SC, -b1c));
            s[nt][3] = ex2f(fmaf(s[nt][3], SC, -b1c));
            sum0 += s[nt][0] + s[nt][1];
            sum1 += s[nt][2] + s[nt][3];
        }
        sum0 += __shfl_xor_sync(0xffffffffu, sum0, 1);
        sum0 += __shfl_xor_sync(0xffffffffu, sum0, 2);
        sum1 += __shfl_xor_sync(0xffffffffu, sum1, 1);
        sum1 += __shfl_xor_sync(0xffffffffu, sum1, 2);
        if (__any_sync(0xffffffffu, chg)) {
            float cr0 = ex2f((om0 - nm0) * SC);
            float cr1 = ex2f((om1 - nm1) * SC);
            l0r *= cr0;
            l1r *= cr1;
            #pragma unroll
            for (int nt = 0; nt < 8; nt++) {
                o[nt][0] *= cr0; o[nt][1] *= cr0;
                o[nt][2] *= cr1; o[nt][3] *= cr1;
            }
        }
        l0r += sum0;
        l1r += sum1;

        // ---- O += P V ----
        #pragma unroll
        for (int kt = 0; kt < 4; kt++) {
            uint32_t a0 = h2(s[2*kt][0],   s[2*kt][1]);
            uint32_t a1 = h2(s[2*kt][2],   s[2*kt][3]);
            uint32_t a2 = h2(s[2*kt+1][0], s[2*kt+1][1]);
            uint32_t a3 = h2(s[2*kt+1][2], s[2*kt+1][3]);
            #pragma unroll
            for (int np = 0; np < 4; np++) {
                int dv   = np * 16 + ((lane >> 4) & 1) * 8 + (lane & 7);
                int scol = kt * 16 + ((lane >> 3) & 1) * 8;
                uint4 vf = ldsm4(so + 8192 + dv * 128 +
                    (((uint32_t)(scol * 2)) ^ ((uint32_t)(dv & 7) << 4)));
                mma_f16(o[2*np][0], o[2*np][1], o[2*np][2], o[2*np][3],
                        a0, a1, a2, a3, vf.x, vf.y);
                mma_f16(o[2*np+1][0], o[2*np+1][1], o[2*np+1][2], o[2*np+1][3],
                        a0, a1, a2, a3, vf.z, vf.w);
            }
        }

        // ---- pipeline: issue chunk ks+3, wait for chunk ks+1 ----
        if (ks + 3 < 16) stage_load((ks + 3) & 3, (ks + 3) * 64);
        if (ks < 15) {
            if (ks < 13)       cp_wait<2>();
            else if (ks == 13) cp_wait<1>();
            else               cp_wait<0>();
            __syncthreads();
        }
    }

    // ---- finalize: stage [q][d] fp16 in smem, write attnT[b][t][c] ----
    __syncthreads();
    __half* sOh = (__half*)(smc + 16384);          // [q128][stride 72]
    float inv0 = 1.f / l0r, inv1 = 1.f / l1r;
    int q0 = wid * 16 + group;
    #pragma unroll
    for (int nt = 0; nt < 8; nt++) {
        int col = nt * 8 + tig * 2;
        sOh[(q0)     * 72 + col]     = __float2half(o[nt][0] * inv0);
        sOh[(q0)     * 72 + col + 1] = __float2half(o[nt][1] * inv0);
        sOh[(q0 + 8) * 72 + col]     = __float2half(o[nt][2] * inv1);
        sOh[(q0 + 8) * 72 + col + 1] = __float2half(o[nt][3] * inv1);
    }
    __syncthreads();
    #pragma unroll
    for (int i = 0; i < 4; i++) {
        int idx = tid + i * 256;
        int q = idx >> 3, d8 = idx & 7;
        uint4 v = *(const uint4*)(sOh + q * 72 + d8 * 8);
        *(uint4*)(attnT + ((size_t)b * TT + t0 + q) * CC + h * HD + d8 * 8) = v;
    }
}

// ---------------------------------------------------------------------------
extern "C" void kernel_launch(void* const* d_in, const int* in_sizes, int n_in,
                              void* d_out, int out_size)
{
    const float* x       = (const float*)d_in[0];
    const float* gn_sc   = (const float*)d_in[1];
    const float* gn_bi   = (const float*)d_in[2];
    const float* qkv_w   = (const float*)d_in[3];
    const float* qkv_b   = (const float*)d_in[4];
    const float* proj_w  = (const float*)d_in[5];
    const float* proj_b  = (const float*)d_in[6];
    float* out = (float*)d_out;

    __half *wq, *wp, *xnT, *qkvh, *attnT;
    cudaGetSymbolAddress((void**)&wq,    g_wq);
    cudaGetSymbolAddress((void**)&wp,    g_wp);
    cudaGetSymbolAddress((void**)&xnT,   g_xnT);
    cudaGetSymbolAddress((void**)&qkvh,  g_qkvh);
    cudaGetSymbolAddress((void**)&attnT, g_attnT);

    const int GEMM_SMEM = 3 * 32768;          // 96KB
    const int ATTN_SMEM = 16384 + 4 * 16384;  // 80KB
    cudaFuncSetAttribute(gemm_tc<true>,
                         cudaFuncAttributeMaxDynamicSharedMemorySize, GEMM_SMEM);
    cudaFuncSetAttribute(gemm_tc<false>,
                         cudaFuncAttributeMaxDynamicSharedMemorySize, GEMM_SMEM);
    cudaFuncSetAttribute(attn_tc,
                         cudaFuncAttributeMaxDynamicSharedMemorySize, ATTN_SMEM);

    cvt_kernel<<<(M_QKV * CC / 8 + 255) / 256, 256>>>(qkv_w, wq, M_QKV * CC / 8);
    cvt_kernel<<<(CC * CC / 8 + 255) / 256, 256>>>(proj_w, wp, CC * CC / 8);

    gn_kernel<<<BB * NG, 256>>>(x, gn_sc, gn_bi, xnT);

    gemm_tc<true><<<dim3(8, M_QKV / 128, BB), 256, GEMM_SMEM>>>(
        wq, xnT, qkv_b, nullptr, qkvh, M_QKV);

    attn_tc<<<dim3(TT / 128, NH, BB), 256, ATTN_SMEM>>>(qkvh, attnT);

    gemm_tc<false><<<dim3(8, CC / 128, BB), 256, GEMM_SMEM>>>(
        wp, attnT, proj_b, x, out, CC);
}